// round 1
// baseline (speedup 1.0000x reference)
#include <cuda_runtime.h>
#include <cuda_bf16.h>

// ---------------------------------------------------------------------------
// mie_51281909514553: 3-layer expert-merged MLP
//   wn = weights / sum(weights)            [E=8]
//   per layer: Wm = sum_e wn_e * W_e ; bm = sum_e wn_e * b_e
//              x  = PReLU(x @ Wm + bm, a)
// Shapes: x [8192,512]; W0 [8,512,1024]; W1 [8,1024,1024]; W2 [8,1024,512]
// Output: [8192,512] fp32
// ---------------------------------------------------------------------------

#define E_EXPERTS 8
#define M_ROWS 8192

// Scratch (no allocations allowed in kernel_launch)
__device__ float g_Wm0[512 * 1024];
__device__ float g_Wm1[1024 * 1024];
__device__ float g_Wm2[1024 * 512];
__device__ float g_bm0[1024];
__device__ float g_bm1[1024];
__device__ float g_bm2[512];
__device__ float g_act0[8192 * 1024];
__device__ float g_act1[8192 * 1024];

// ---------------------------------------------------------------------------
// Expert-merge: Wm[i] = sum_e (w_e / sum(w)) * W[e][i]; same for bias.
// wsize = K*N elements, bsize = N elements.
// ---------------------------------------------------------------------------
__global__ void merge_kernel(const float* __restrict__ weights,
                             const float* __restrict__ W,
                             const float* __restrict__ b,
                             float* __restrict__ Wm,
                             float* __restrict__ bm,
                             int wsize, int bsize) {
    float s = 0.f;
#pragma unroll
    for (int e = 0; e < E_EXPERTS; e++) s += weights[e];
    const float inv = 1.f / s;

    int i = blockIdx.x * blockDim.x + threadIdx.x;
    if (i < wsize) {
        float acc = 0.f;
#pragma unroll
        for (int e = 0; e < E_EXPERTS; e++)
            acc += (weights[e] * inv) * W[(long)e * wsize + i];
        Wm[i] = acc;
    }
    if (i < bsize) {
        float acc = 0.f;
#pragma unroll
        for (int e = 0; e < E_EXPERTS; e++)
            acc += (weights[e] * inv) * b[e * bsize + i];
        bm[i] = acc;
    }
}

// ---------------------------------------------------------------------------
// Tiled SGEMM with fused bias + PReLU epilogue.
// C[M,N] = PReLU(A[M,K] @ B[K,N] + bias[N], alpha[N])
// BM=BN=128, BK=8, 256 threads, 8x8 microtile per thread.
// M % 128 == 0, N % 128 == 0, K % 8 == 0 guaranteed by problem shapes.
// ---------------------------------------------------------------------------
#define BM 128
#define BN 128
#define BK 8
#define TM 8
#define TN 8

__global__ __launch_bounds__(256, 2)
void gemm_bias_prelu(const float* __restrict__ A,
                     const float* __restrict__ B,
                     const float* __restrict__ bias,
                     const float* __restrict__ alpha,
                     float* __restrict__ C,
                     int M, int N, int K) {
    __shared__ float As[BK][BM];   // transposed A tile
    __shared__ float Bs[BK][BN];

    const int tid = threadIdx.x;
    const int block_m = blockIdx.y * BM;
    const int block_n = blockIdx.x * BN;

    const int tm = (tid / 16) * TM;   // 0..120
    const int tn = (tid % 16) * TN;   // 0..120

    // A tile load mapping: 128 rows x 8 cols = 256 float4
    const int arow = tid >> 1;            // 0..127
    const int acol = (tid & 1) * 4;       // 0 or 4
    // B tile load mapping: 8 rows x 128 cols = 256 float4
    const int brow = tid >> 5;            // 0..7
    const int bcol = (tid & 31) * 4;      // 0..124

    float acc[TM][TN];
#pragma unroll
    for (int i = 0; i < TM; i++)
#pragma unroll
        for (int j = 0; j < TN; j++) acc[i][j] = 0.f;

    for (int k0 = 0; k0 < K; k0 += BK) {
        float4 a4 = *reinterpret_cast<const float4*>(
            &A[(long)(block_m + arow) * K + k0 + acol]);
        As[acol + 0][arow] = a4.x;
        As[acol + 1][arow] = a4.y;
        As[acol + 2][arow] = a4.z;
        As[acol + 3][arow] = a4.w;

        float4 b4 = *reinterpret_cast<const float4*>(
            &B[(long)(k0 + brow) * N + block_n + bcol]);
        *reinterpret_cast<float4*>(&Bs[brow][bcol]) = b4;

        __syncthreads();

#pragma unroll
        for (int k = 0; k < BK; k++) {
            float ra[TM], rb[TN];
#pragma unroll
            for (int i = 0; i < TM; i++) ra[i] = As[k][tm + i];
#pragma unroll
            for (int j = 0; j < TN; j++) rb[j] = Bs[k][tn + j];
#pragma unroll
            for (int i = 0; i < TM; i++)
#pragma unroll
                for (int j = 0; j < TN; j++)
                    acc[i][j] = fmaf(ra[i], rb[j], acc[i][j]);
        }
        __syncthreads();
    }

    // Fused bias + PReLU epilogue, vectorized stores
#pragma unroll
    for (int i = 0; i < TM; i++) {
        const long row = block_m + tm + i;
#pragma unroll
        for (int j = 0; j < TN; j += 4) {
            const int col = block_n + tn + j;
            float4 v;
            float b0 = bias[col + 0], b1 = bias[col + 1],
                  b2 = bias[col + 2], b3 = bias[col + 3];
            float p0 = alpha[col + 0], p1 = alpha[col + 1],
                  p2 = alpha[col + 2], p3 = alpha[col + 3];
            float s0 = acc[i][j + 0] + b0;
            float s1 = acc[i][j + 1] + b1;
            float s2 = acc[i][j + 2] + b2;
            float s3 = acc[i][j + 3] + b3;
            v.x = s0 >= 0.f ? s0 : p0 * s0;
            v.y = s1 >= 0.f ? s1 : p1 * s1;
            v.z = s2 >= 0.f ? s2 : p2 * s2;
            v.w = s3 >= 0.f ? s3 : p3 * s3;
            *reinterpret_cast<float4*>(&C[row * N + col]) = v;
        }
    }
}

// ---------------------------------------------------------------------------
// Launch
// Input order (metadata): x, weights, W0, b0, a0, W1, b1, a1, W2, b2, a2
// ---------------------------------------------------------------------------
extern "C" void kernel_launch(void* const* d_in, const int* in_sizes, int n_in,
                              void* d_out, int out_size) {
    const float* x       = (const float*)d_in[0];
    const float* weights = (const float*)d_in[1];
    const float* W0 = (const float*)d_in[2];
    const float* b0 = (const float*)d_in[3];
    const float* a0 = (const float*)d_in[4];
    const float* W1 = (const float*)d_in[5];
    const float* b1 = (const float*)d_in[6];
    const float* a1 = (const float*)d_in[7];
    const float* W2 = (const float*)d_in[8];
    const float* b2 = (const float*)d_in[9];
    const float* a2 = (const float*)d_in[10];
    float* out = (float*)d_out;

    // Device addresses of scratch symbols (host-side lookup; capture-safe)
    float *pWm0, *pWm1, *pWm2, *pbm0, *pbm1, *pbm2, *pact0, *pact1;
    cudaGetSymbolAddress((void**)&pWm0, g_Wm0);
    cudaGetSymbolAddress((void**)&pWm1, g_Wm1);
    cudaGetSymbolAddress((void**)&pWm2, g_Wm2);
    cudaGetSymbolAddress((void**)&pbm0, g_bm0);
    cudaGetSymbolAddress((void**)&pbm1, g_bm1);
    cudaGetSymbolAddress((void**)&pbm2, g_bm2);
    cudaGetSymbolAddress((void**)&pact0, g_act0);
    cudaGetSymbolAddress((void**)&pact1, g_act1);

    // 1) merge expert weights (tiny)
    {
        int ws = 512 * 1024, bs = 1024;
        merge_kernel<<<(ws + 255) / 256, 256>>>(weights, W0, b0, pWm0, pbm0, ws, bs);
    }
    {
        int ws = 1024 * 1024, bs = 1024;
        merge_kernel<<<(ws + 255) / 256, 256>>>(weights, W1, b1, pWm1, pbm1, ws, bs);
    }
    {
        int ws = 1024 * 512, bs = 512;
        merge_kernel<<<(ws + 255) / 256, 256>>>(weights, W2, b2, pWm2, pbm2, ws, bs);
    }

    // 2) three fused GEMM + bias + PReLU layers
    {
        dim3 grid(1024 / BN, M_ROWS / BM);
        gemm_bias_prelu<<<grid, 256>>>(x, pWm0, pbm0, a0, pact0,
                                       M_ROWS, 1024, 512);
    }
    {
        dim3 grid(1024 / BN, M_ROWS / BM);
        gemm_bias_prelu<<<grid, 256>>>(pact0, pWm1, pbm1, a1, pact1,
                                       M_ROWS, 1024, 1024);
    }
    {
        dim3 grid(512 / BN, M_ROWS / BM);
        gemm_bias_prelu<<<grid, 256>>>(pact1, pWm2, pbm2, a2, out,
                                       M_ROWS, 512, 1024);
    }
}

// round 3
// speedup vs baseline: 2.0461x; 2.0461x over previous
#include <cuda_runtime.h>
#include <cuda_bf16.h>
#include <cstdint>

// ===========================================================================
// mie_51281909514553 — 3-layer expert-merged MLP, bf16-split HMMA (mma.sync)
//   wn = weights/sum(weights); per layer: x = PReLU(x @ Wm + bm, a)
//   fp32 emulated as bf16 hi+lo: D += Ah*Bh + Ah*Bl + Al*Bh (fp32 accumulate)
// NOTE: tcgen05 is rejected by this toolchain (PTX target compute_103, no 'a')
//       so we use base-ISA mma.sync.m16n8k16 bf16 (HMMA pipe).
// ===========================================================================

#define M_ROWS 8192
#define E_EXPERTS 8

// ------------------------------ scratch (no allocs allowed) ----------------
__device__ __nv_bfloat16 g_xhi[8192 * 512];
__device__ __nv_bfloat16 g_xlo[8192 * 512];
__device__ __nv_bfloat16 g_h0[8192 * 1024];
__device__ __nv_bfloat16 g_l0[8192 * 1024];
__device__ __nv_bfloat16 g_h1[8192 * 1024];
__device__ __nv_bfloat16 g_l1[8192 * 1024];
__device__ __nv_bfloat16 g_wt0h[1024 * 512];   // merged W^T: [N][K]
__device__ __nv_bfloat16 g_wt0l[1024 * 512];
__device__ __nv_bfloat16 g_wt1h[1024 * 1024];
__device__ __nv_bfloat16 g_wt1l[1024 * 1024];
__device__ __nv_bfloat16 g_wt2h[512 * 1024];
__device__ __nv_bfloat16 g_wt2l[512 * 1024];
__device__ float g_bm0[1024];
__device__ float g_bm1[1024];
__device__ float g_bm2[512];

// ------------------------------ helpers ------------------------------------
__device__ __forceinline__ uint32_t smem_u32(const void* p) {
    uint32_t a;
    asm("{ .reg .u64 t; cvta.to.shared.u64 t, %1; cvt.u32.u64 %0, t; }"
        : "=r"(a) : "l"(p));
    return a;
}

__device__ __forceinline__ void cp16(uint32_t s, const void* g) {
    asm volatile("cp.async.cg.shared.global [%0], [%1], 16;" :: "r"(s), "l"(g) : "memory");
}
#define CP_COMMIT() asm volatile("cp.async.commit_group;" ::: "memory")
#define CP_WAIT(n)  asm volatile("cp.async.wait_group %0;" :: "n"(n) : "memory")

__device__ __forceinline__ void ldsm4(uint32_t& r0, uint32_t& r1,
                                      uint32_t& r2, uint32_t& r3, uint32_t a) {
    asm volatile("ldmatrix.sync.aligned.m8n8.x4.shared.b16 {%0,%1,%2,%3}, [%4];"
                 : "=r"(r0), "=r"(r1), "=r"(r2), "=r"(r3) : "r"(a));
}

__device__ __forceinline__ void mma_bf16(float* c, const uint32_t* a, const uint32_t* b) {
    asm volatile(
        "mma.sync.aligned.m16n8k16.row.col.f32.bf16.bf16.f32 "
        "{%0,%1,%2,%3}, {%4,%5,%6,%7}, {%8,%9}, {%0,%1,%2,%3};"
        : "+f"(c[0]), "+f"(c[1]), "+f"(c[2]), "+f"(c[3])
        : "r"(a[0]), "r"(a[1]), "r"(a[2]), "r"(a[3]), "r"(b[0]), "r"(b[1]));
}

// ------------------------------ merge+transpose+split ----------------------
__global__ void merge_split_w(const float* __restrict__ weights,
                              const float* __restrict__ W,
                              const float* __restrict__ b,
                              __nv_bfloat16* __restrict__ Th,
                              __nv_bfloat16* __restrict__ Tl,
                              float* __restrict__ bm,
                              int K, int N) {
    __shared__ float tile[32][33];
    float s = 0.f;
#pragma unroll
    for (int e = 0; e < E_EXPERTS; e++) s += weights[e];
    const float inv = 1.f / s;
    float wn[E_EXPERTS];
#pragma unroll
    for (int e = 0; e < E_EXPERTS; e++) wn[e] = weights[e] * inv;

    const int k0 = blockIdx.x * 32, n0 = blockIdx.y * 32;
    for (int ty = threadIdx.y; ty < 32; ty += 8) {
        int k = k0 + ty, n = n0 + threadIdx.x;
        float acc = 0.f;
#pragma unroll
        for (int e = 0; e < E_EXPERTS; e++)
            acc += wn[e] * W[(size_t)e * K * N + (size_t)k * N + n];
        tile[ty][threadIdx.x] = acc;
    }
    if (blockIdx.x == 0 && threadIdx.y == 0) {
        int n = n0 + threadIdx.x;
        float acc = 0.f;
#pragma unroll
        for (int e = 0; e < E_EXPERTS; e++) acc += wn[e] * b[e * N + n];
        bm[n] = acc;
    }
    __syncthreads();
    for (int ty = threadIdx.y; ty < 32; ty += 8) {
        int n = n0 + ty, k = k0 + threadIdx.x;
        float v = tile[threadIdx.x][ty];
        __nv_bfloat16 h = __float2bfloat16(v);
        __nv_bfloat16 l = __float2bfloat16(v - __bfloat162float(h));
        Th[(size_t)n * K + k] = h;
        Tl[(size_t)n * K + k] = l;
    }
}

__global__ void split_x(const float* __restrict__ x,
                        __nv_bfloat16* __restrict__ xh,
                        __nv_bfloat16* __restrict__ xl, int n) {
    int i = blockIdx.x * blockDim.x + threadIdx.x;
    if (i < n) {
        float v = x[i];
        __nv_bfloat16 h = __float2bfloat16(v);
        xh[i] = h;
        xl[i] = __float2bfloat16(v - __bfloat162float(h));
    }
}

// ------------------------------ HMMA GEMM ----------------------------------
// BM=128, BN=128, BK=32, 256 threads (8 warps: 4 along M x 2 along N).
// Warp tile 32(m) x 64(n). 3-stage cp.async pipeline.
// smem tiles row-major with padded stride 40 bf16 (80B) -> conflict-free.
#define BK 32
#define STAGES 3
#define TSTRIDE 40                         // bf16 elements per smem row
#define TILE_B (128 * TSTRIDE * 2)         // 10240 bytes per tile
#define STAGE_B (4 * TILE_B)               // Ah, Al, Bh, Bl
#define SMEM_DYN (STAGES * STAGE_B)        // 122880 bytes

template <int OUT_BF16>
__global__ __launch_bounds__(256, 1)
void gemm_hmma(const __nv_bfloat16* __restrict__ Ah, const __nv_bfloat16* __restrict__ Al,
               const __nv_bfloat16* __restrict__ Bh, const __nv_bfloat16* __restrict__ Bl,
               const float* __restrict__ bias, const float* __restrict__ alpha,
               float* __restrict__ outF,
               __nv_bfloat16* __restrict__ outH, __nv_bfloat16* __restrict__ outL,
               int M, int N, int K) {
    extern __shared__ char smem[];
    const uint32_t sbase = smem_u32(smem);

    const int tid = threadIdx.x;
    const int wid = tid >> 5, lane = tid & 31;
    const int gid = lane >> 2, tg = lane & 3;
    const int warp_m = (wid & 3) * 32;
    const int warp_n = (wid >> 2) * 64;
    const int block_m = blockIdx.y * 128;
    const int block_n = blockIdx.x * 128;

    // ldmatrix lane addresses (byte offsets within a tile)
    // A: 16x16 tile at (warp_m + mt*16, kstep*16): lane -> row lane&15, col (lane>>4)*8
    uint32_t a_off[2];
#pragma unroll
    for (int mt = 0; mt < 2; mt++)
        a_off[mt] = ((warp_m + mt * 16 + (lane & 15)) * TSTRIDE + (lane >> 4) * 8) * 2;
    // B: two n8 tiles per ldmatrix.x4: n = warp_n + nt2*16 + (lane>>4)*8 + (lane&7),
    //    k = ((lane>>3)&1)*8
    uint32_t b_off[4];
#pragma unroll
    for (int nt2 = 0; nt2 < 4; nt2++)
        b_off[nt2] = ((warp_n + nt2 * 16 + (lane >> 4) * 8 + (lane & 7)) * TSTRIDE +
                      ((lane >> 3) & 1) * 8) * 2;

    float acc[2][8][4];
#pragma unroll
    for (int mt = 0; mt < 2; mt++)
#pragma unroll
        for (int nt = 0; nt < 8; nt++)
#pragma unroll
            for (int j = 0; j < 4; j++) acc[mt][nt][j] = 0.f;

    const int nK = K / BK;

    // stage tile bases
    auto stg = [&](int s) { return sbase + (uint32_t)s * STAGE_B; };

    // cp.async tile fill: tile = 128 rows x 32 cols bf16, 4 x 16B chunks per row
    auto load_stage = [&](int ki, int s) {
        const int k0 = ki * BK;
        const uint32_t base = stg(s);
        const __nv_bfloat16* gsrc[4] = {Ah, Al, Bh, Bl};
        const int row0[4] = {block_m, block_m, block_n, block_n};
#pragma unroll
        for (int t = 0; t < 4; t++) {
#pragma unroll
            for (int j = 0; j < 2; j++) {
                int chunk = j * 256 + tid;        // 0..511
                int r = chunk >> 2, c = chunk & 3;
                cp16(base + t * TILE_B + r * (TSTRIDE * 2) + c * 16,
                     gsrc[t] + (size_t)(row0[t] + r) * K + k0 + c * 8);
            }
        }
    };

#pragma unroll
    for (int s = 0; s < STAGES; s++) {
        if (s < nK) load_stage(s, s);
        CP_COMMIT();
    }

    for (int i = 0; i < nK; i++) {
        const int s = i % STAGES;
        CP_WAIT(STAGES - 1);
        __syncthreads();

        const uint32_t tAh = stg(s);
        const uint32_t tAl = tAh + TILE_B;
        const uint32_t tBh = tAl + TILE_B;
        const uint32_t tBl = tBh + TILE_B;

#pragma unroll
        for (int ks = 0; ks < 2; ks++) {
            const uint32_t kb = ks * 32;   // 16 bf16 = 32 bytes
            uint32_t ah[2][4], al[2][4];
#pragma unroll
            for (int mt = 0; mt < 2; mt++) {
                ldsm4(ah[mt][0], ah[mt][1], ah[mt][2], ah[mt][3], tAh + a_off[mt] + kb);
                ldsm4(al[mt][0], al[mt][1], al[mt][2], al[mt][3], tAl + a_off[mt] + kb);
            }
            uint32_t bh[8][2], bl[8][2];
#pragma unroll
            for (int nt2 = 0; nt2 < 4; nt2++) {
                ldsm4(bh[2 * nt2][0], bh[2 * nt2][1], bh[2 * nt2 + 1][0], bh[2 * nt2 + 1][1],
                      tBh + b_off[nt2] + kb);
                ldsm4(bl[2 * nt2][0], bl[2 * nt2][1], bl[2 * nt2 + 1][0], bl[2 * nt2 + 1][1],
                      tBl + b_off[nt2] + kb);
            }
#pragma unroll
            for (int mt = 0; mt < 2; mt++)
#pragma unroll
                for (int nt = 0; nt < 8; nt++) {
                    mma_bf16(acc[mt][nt], ah[mt], bh[nt]);
                    mma_bf16(acc[mt][nt], ah[mt], bl[nt]);
                    mma_bf16(acc[mt][nt], al[mt], bh[nt]);
                }
        }

        __syncthreads();
        if (i + STAGES < nK) load_stage(i + STAGES, s);
        CP_COMMIT();
    }

    // ---------------- epilogue: bias + PReLU, store straight from regs ------
#pragma unroll
    for (int mt = 0; mt < 2; mt++) {
        const int r0 = block_m + warp_m + mt * 16 + gid;
#pragma unroll
        for (int nt = 0; nt < 8; nt++) {
            const int n = block_n + warp_n + nt * 8 + tg * 2;
            const float b0 = __ldg(&bias[n]),  b1 = __ldg(&bias[n + 1]);
            const float p0 = __ldg(&alpha[n]), p1 = __ldg(&alpha[n + 1]);
#pragma unroll
            for (int half = 0; half < 2; half++) {
                const int r = r0 + half * 8;
                float v0 = acc[mt][nt][half * 2 + 0] + b0;
                float v1 = acc[mt][nt][half * 2 + 1] + b1;
                v0 = v0 >= 0.f ? v0 : p0 * v0;
                v1 = v1 >= 0.f ? v1 : p1 * v1;
                if (OUT_BF16) {
                    __nv_bfloat16 h0 = __float2bfloat16(v0);
                    __nv_bfloat16 h1 = __float2bfloat16(v1);
                    __nv_bfloat162 hh, ll;
                    hh.x = h0; hh.y = h1;
                    ll.x = __float2bfloat16(v0 - __bfloat162float(h0));
                    ll.y = __float2bfloat16(v1 - __bfloat162float(h1));
                    *reinterpret_cast<__nv_bfloat162*>(&outH[(size_t)r * N + n]) = hh;
                    *reinterpret_cast<__nv_bfloat162*>(&outL[(size_t)r * N + n]) = ll;
                } else {
                    float2 o; o.x = v0; o.y = v1;
                    *reinterpret_cast<float2*>(&outF[(size_t)r * N + n]) = o;
                }
            }
        }
    }
}

// ------------------------------ launch -------------------------------------
extern "C" void kernel_launch(void* const* d_in, const int* in_sizes, int n_in,
                              void* d_out, int out_size) {
    const float* x       = (const float*)d_in[0];
    const float* weights = (const float*)d_in[1];
    const float* W0 = (const float*)d_in[2];
    const float* b0 = (const float*)d_in[3];
    const float* a0 = (const float*)d_in[4];
    const float* W1 = (const float*)d_in[5];
    const float* b1 = (const float*)d_in[6];
    const float* a1 = (const float*)d_in[7];
    const float* W2 = (const float*)d_in[8];
    const float* b2 = (const float*)d_in[9];
    const float* a2 = (const float*)d_in[10];
    float* out = (float*)d_out;

    auto sym = [](const void* s) {
        void* p = nullptr;
        cudaGetSymbolAddress(&p, (const void*)s);
        return p;
    };
    __nv_bfloat16* xhi = (__nv_bfloat16*)sym(g_xhi);
    __nv_bfloat16* xlo = (__nv_bfloat16*)sym(g_xlo);
    __nv_bfloat16* h0 = (__nv_bfloat16*)sym(g_h0);
    __nv_bfloat16* l0 = (__nv_bfloat16*)sym(g_l0);
    __nv_bfloat16* h1 = (__nv_bfloat16*)sym(g_h1);
    __nv_bfloat16* l1 = (__nv_bfloat16*)sym(g_l1);
    __nv_bfloat16* wt0h = (__nv_bfloat16*)sym(g_wt0h);
    __nv_bfloat16* wt0l = (__nv_bfloat16*)sym(g_wt0l);
    __nv_bfloat16* wt1h = (__nv_bfloat16*)sym(g_wt1h);
    __nv_bfloat16* wt1l = (__nv_bfloat16*)sym(g_wt1l);
    __nv_bfloat16* wt2h = (__nv_bfloat16*)sym(g_wt2h);
    __nv_bfloat16* wt2l = (__nv_bfloat16*)sym(g_wt2l);
    float* bm0 = (float*)sym(g_bm0);
    float* bm1 = (float*)sym(g_bm1);
    float* bm2 = (float*)sym(g_bm2);

    cudaFuncSetAttribute(gemm_hmma<1>, cudaFuncAttributeMaxDynamicSharedMemorySize, SMEM_DYN);
    cudaFuncSetAttribute(gemm_hmma<0>, cudaFuncAttributeMaxDynamicSharedMemorySize, SMEM_DYN);

    // merge + transpose + split weights
    merge_split_w<<<dim3(512 / 32, 1024 / 32), dim3(32, 8)>>>(weights, W0, b0, wt0h, wt0l, bm0, 512, 1024);
    merge_split_w<<<dim3(1024 / 32, 1024 / 32), dim3(32, 8)>>>(weights, W1, b1, wt1h, wt1l, bm1, 1024, 1024);
    merge_split_w<<<dim3(1024 / 32, 512 / 32), dim3(32, 8)>>>(weights, W2, b2, wt2h, wt2l, bm2, 1024, 512);

    // split input activations to bf16 hi/lo
    split_x<<<(8192 * 512 + 255) / 256, 256>>>(x, xhi, xlo, 8192 * 512);

    // layer 0: [8192,512] @ [512,1024]
    gemm_hmma<1><<<dim3(1024 / 128, M_ROWS / 128), 256, SMEM_DYN>>>(
        xhi, xlo, wt0h, wt0l, bm0, a0, nullptr, h0, l0, M_ROWS, 1024, 512);
    // layer 1: [8192,1024] @ [1024,1024]
    gemm_hmma<1><<<dim3(1024 / 128, M_ROWS / 128), 256, SMEM_DYN>>>(
        h0, l0, wt1h, wt1l, bm1, a1, nullptr, h1, l1, M_ROWS, 1024, 1024);
    // layer 2: [8192,1024] @ [1024,512] -> fp32 out
    gemm_hmma<0><<<dim3(512 / 128, M_ROWS / 128), 256, SMEM_DYN>>>(
        h1, l1, wt2h, wt2l, bm2, a2, out, nullptr, nullptr, M_ROWS, 512, 1024);
}

// round 4
// speedup vs baseline: 2.3336x; 1.1405x over previous
#include <cuda_runtime.h>
#include <cuda_bf16.h>
#include <cstdint>

// ===========================================================================
// mie_51281909514553 — 3-layer expert-merged MLP, bf16-split HMMA (mma.sync)
//   wn = weights/sum(weights); per layer: x = PReLU(x @ Wm + bm, a)
//   fp32 emulated as bf16 hi+lo: D += Ah*Bh + Ah*Bl + Al*Bh (fp32 accumulate)
// R4: 512-thread CTA (16 warps, 4/SMSP), BM=128 BN=256, single-sync 3-stage
//     cp.async pipeline.
// ===========================================================================

#define M_ROWS 8192
#define E_EXPERTS 8

// ------------------------------ scratch (no allocs allowed) ----------------
__device__ __nv_bfloat16 g_xhi[8192 * 512];
__device__ __nv_bfloat16 g_xlo[8192 * 512];
__device__ __nv_bfloat16 g_h0[8192 * 1024];
__device__ __nv_bfloat16 g_l0[8192 * 1024];
__device__ __nv_bfloat16 g_h1[8192 * 1024];
__device__ __nv_bfloat16 g_l1[8192 * 1024];
__device__ __nv_bfloat16 g_wt0h[1024 * 512];   // merged W^T: [N][K]
__device__ __nv_bfloat16 g_wt0l[1024 * 512];
__device__ __nv_bfloat16 g_wt1h[1024 * 1024];
__device__ __nv_bfloat16 g_wt1l[1024 * 1024];
__device__ __nv_bfloat16 g_wt2h[512 * 1024];
__device__ __nv_bfloat16 g_wt2l[512 * 1024];
__device__ float g_bm0[1024];
__device__ float g_bm1[1024];
__device__ float g_bm2[512];

// ------------------------------ helpers ------------------------------------
__device__ __forceinline__ uint32_t smem_u32(const void* p) {
    uint32_t a;
    asm("{ .reg .u64 t; cvta.to.shared.u64 t, %1; cvt.u32.u64 %0, t; }"
        : "=r"(a) : "l"(p));
    return a;
}

__device__ __forceinline__ void cp16(uint32_t s, const void* g) {
    asm volatile("cp.async.cg.shared.global [%0], [%1], 16;" :: "r"(s), "l"(g) : "memory");
}
#define CP_COMMIT() asm volatile("cp.async.commit_group;" ::: "memory")
#define CP_WAIT(n)  asm volatile("cp.async.wait_group %0;" :: "n"(n) : "memory")

__device__ __forceinline__ void ldsm4(uint32_t& r0, uint32_t& r1,
                                      uint32_t& r2, uint32_t& r3, uint32_t a) {
    asm volatile("ldmatrix.sync.aligned.m8n8.x4.shared.b16 {%0,%1,%2,%3}, [%4];"
                 : "=r"(r0), "=r"(r1), "=r"(r2), "=r"(r3) : "r"(a));
}

__device__ __forceinline__ void mma_bf16(float* c, const uint32_t* a, const uint32_t* b) {
    asm volatile(
        "mma.sync.aligned.m16n8k16.row.col.f32.bf16.bf16.f32 "
        "{%0,%1,%2,%3}, {%4,%5,%6,%7}, {%8,%9}, {%0,%1,%2,%3};"
        : "+f"(c[0]), "+f"(c[1]), "+f"(c[2]), "+f"(c[3])
        : "r"(a[0]), "r"(a[1]), "r"(a[2]), "r"(a[3]), "r"(b[0]), "r"(b[1]));
}

// ------------------------------ merge+transpose+split ----------------------
__global__ void merge_split_w(const float* __restrict__ weights,
                              const float* __restrict__ W,
                              const float* __restrict__ b,
                              __nv_bfloat16* __restrict__ Th,
                              __nv_bfloat16* __restrict__ Tl,
                              float* __restrict__ bm,
                              int K, int N) {
    __shared__ float tile[32][33];
    float s = 0.f;
#pragma unroll
    for (int e = 0; e < E_EXPERTS; e++) s += weights[e];
    const float inv = 1.f / s;
    float wn[E_EXPERTS];
#pragma unroll
    for (int e = 0; e < E_EXPERTS; e++) wn[e] = weights[e] * inv;

    const int k0 = blockIdx.x * 32, n0 = blockIdx.y * 32;
    for (int ty = threadIdx.y; ty < 32; ty += 8) {
        int k = k0 + ty, n = n0 + threadIdx.x;
        float acc = 0.f;
#pragma unroll
        for (int e = 0; e < E_EXPERTS; e++)
            acc += wn[e] * W[(size_t)e * K * N + (size_t)k * N + n];
        tile[ty][threadIdx.x] = acc;
    }
    if (blockIdx.x == 0 && threadIdx.y == 0) {
        int n = n0 + threadIdx.x;
        float acc = 0.f;
#pragma unroll
        for (int e = 0; e < E_EXPERTS; e++) acc += wn[e] * b[e * N + n];
        bm[n] = acc;
    }
    __syncthreads();
    for (int ty = threadIdx.y; ty < 32; ty += 8) {
        int n = n0 + ty, k = k0 + threadIdx.x;
        float v = tile[threadIdx.x][ty];
        __nv_bfloat16 h = __float2bfloat16(v);
        __nv_bfloat16 l = __float2bfloat16(v - __bfloat162float(h));
        Th[(size_t)n * K + k] = h;
        Tl[(size_t)n * K + k] = l;
    }
}

__global__ void split_x(const float* __restrict__ x,
                        __nv_bfloat16* __restrict__ xh,
                        __nv_bfloat16* __restrict__ xl, int n) {
    int i = blockIdx.x * blockDim.x + threadIdx.x;
    if (i < n) {
        float v = x[i];
        __nv_bfloat16 h = __float2bfloat16(v);
        xh[i] = h;
        xl[i] = __float2bfloat16(v - __bfloat162float(h));
    }
}

// ------------------------------ HMMA GEMM ----------------------------------
// BM=128, BN=256, BK=32, 512 threads (16 warps: 4 along M x 4 along N).
// Warp tile 32(m) x 64(n). 3-stage cp.async pipeline, ONE sync per chunk.
// smem tiles row-major, padded stride 40 bf16 (80B).
#define BK 32
#define STAGES 3
#define TSTRIDE 40                          // bf16 elements per smem row
#define ROWB (TSTRIDE * 2)                  // 80 bytes
#define TILE_A_B (128 * ROWB)               // 10240 bytes
#define TILE_B_B (256 * ROWB)               // 20480 bytes
#define STAGE_B (2 * TILE_A_B + 2 * TILE_B_B)  // 61440 bytes
#define SMEM_DYN (STAGES * STAGE_B)            // 184320 bytes

template <int OUT_BF16>
__global__ __launch_bounds__(512, 1)
void gemm_hmma(const __nv_bfloat16* __restrict__ Ah, const __nv_bfloat16* __restrict__ Al,
               const __nv_bfloat16* __restrict__ Bh, const __nv_bfloat16* __restrict__ Bl,
               const float* __restrict__ bias, const float* __restrict__ alpha,
               float* __restrict__ outF,
               __nv_bfloat16* __restrict__ outH, __nv_bfloat16* __restrict__ outL,
               int M, int N, int K) {
    extern __shared__ char smem[];
    const uint32_t sbase = smem_u32(smem);

    const int tid = threadIdx.x;
    const int wid = tid >> 5, lane = tid & 31;
    const int gid = lane >> 2, tg = lane & 3;
    const int warp_m = (wid & 3) * 32;      // 0..96
    const int warp_n = (wid >> 2) * 64;     // 0..192
    const int block_m = blockIdx.y * 128;
    const int block_n = blockIdx.x * 256;

    // ldmatrix lane byte-offsets within a tile
    uint32_t a_off[2];
#pragma unroll
    for (int mt = 0; mt < 2; mt++)
        a_off[mt] = ((warp_m + mt * 16 + (lane & 15)) * TSTRIDE + (lane >> 4) * 8) * 2;
    uint32_t b_off[4];
#pragma unroll
    for (int nt2 = 0; nt2 < 4; nt2++)
        b_off[nt2] = ((warp_n + nt2 * 16 + (lane >> 4) * 8 + (lane & 7)) * TSTRIDE +
                      ((lane >> 3) & 1) * 8) * 2;

    float acc[2][8][4];
#pragma unroll
    for (int mt = 0; mt < 2; mt++)
#pragma unroll
        for (int nt = 0; nt < 8; nt++)
#pragma unroll
            for (int j = 0; j < 4; j++) acc[mt][nt][j] = 0.f;

    const int nK = K / BK;

    auto stg = [&](int s) { return sbase + (uint32_t)s * STAGE_B; };

    // A tiles: 128 rows x 4 chunks = 512 (1 iter); B tiles: 256 x 4 = 1024 (2 iters)
    auto load_stage = [&](int ki, int s) {
        const int k0 = ki * BK;
        const uint32_t base = stg(s);
        {   // Ah, Al
            int r = tid >> 2, c = tid & 3;
            uint32_t so = (uint32_t)(r * ROWB + c * 16);
            const size_t go = (size_t)(block_m + r) * K + k0 + c * 8;
            cp16(base + so, Ah + go);
            cp16(base + TILE_A_B + so, Al + go);
        }
        {   // Bh, Bl
#pragma unroll
            for (int j = 0; j < 2; j++) {
                int chunk = j * 512 + tid;
                int r = chunk >> 2, c = chunk & 3;
                uint32_t so = (uint32_t)(r * ROWB + c * 16);
                const size_t go = (size_t)(block_n + r) * K + k0 + c * 8;
                cp16(base + 2 * TILE_A_B + so, Bh + go);
                cp16(base + 2 * TILE_A_B + TILE_B_B + so, Bl + go);
            }
        }
    };

    // preload chunks 0..STAGES-2
#pragma unroll
    for (int s = 0; s < STAGES - 1; s++) {
        if (s < nK) load_stage(s, s);
        CP_COMMIT();
    }

    for (int i = 0; i < nK; i++) {
        CP_WAIT(STAGES - 2);        // chunk i resident
        __syncthreads();            // all warps done with chunk i-1's slot

        // prefetch chunk i+STAGES-1 into the slot freed by chunk i-1
        const int pf = i + STAGES - 1;
        if (pf < nK) load_stage(pf, pf % STAGES);
        CP_COMMIT();

        const uint32_t tAh = stg(i % STAGES);
        const uint32_t tAl = tAh + TILE_A_B;
        const uint32_t tBh = tAl + TILE_A_B;
        const uint32_t tBl = tBh + TILE_B_B;

#pragma unroll
        for (int ks = 0; ks < 2; ks++) {
            const uint32_t kb = ks * 32;   // 16 bf16 = 32 bytes
            uint32_t ah[2][4], al[2][4];
#pragma unroll
            for (int mt = 0; mt < 2; mt++) {
                ldsm4(ah[mt][0], ah[mt][1], ah[mt][2], ah[mt][3], tAh + a_off[mt] + kb);
                ldsm4(al[mt][0], al[mt][1], al[mt][2], al[mt][3], tAl + a_off[mt] + kb);
            }
#pragma unroll
            for (int nt2 = 0; nt2 < 4; nt2++) {
                uint32_t bh[2][2], bl[2][2];
                ldsm4(bh[0][0], bh[0][1], bh[1][0], bh[1][1], tBh + b_off[nt2] + kb);
                ldsm4(bl[0][0], bl[0][1], bl[1][0], bl[1][1], tBl + b_off[nt2] + kb);
#pragma unroll
                for (int h = 0; h < 2; h++) {
                    const int nt = 2 * nt2 + h;
#pragma unroll
                    for (int mt = 0; mt < 2; mt++) {
                        mma_bf16(acc[mt][nt], ah[mt], bh[h]);
                        mma_bf16(acc[mt][nt], ah[mt], bl[h]);
                        mma_bf16(acc[mt][nt], al[mt], bh[h]);
                    }
                }
            }
        }
    }

    // ---------------- epilogue: bias + PReLU, store straight from regs ------
#pragma unroll
    for (int mt = 0; mt < 2; mt++) {
        const int r0 = block_m + warp_m + mt * 16 + gid;
#pragma unroll
        for (int nt = 0; nt < 8; nt++) {
            const int n = block_n + warp_n + nt * 8 + tg * 2;
            const float b0 = __ldg(&bias[n]),  b1 = __ldg(&bias[n + 1]);
            const float p0 = __ldg(&alpha[n]), p1 = __ldg(&alpha[n + 1]);
#pragma unroll
            for (int half = 0; half < 2; half++) {
                const int r = r0 + half * 8;
                float v0 = acc[mt][nt][half * 2 + 0] + b0;
                float v1 = acc[mt][nt][half * 2 + 1] + b1;
                v0 = v0 >= 0.f ? v0 : p0 * v0;
                v1 = v1 >= 0.f ? v1 : p1 * v1;
                if (OUT_BF16) {
                    __nv_bfloat16 h0 = __float2bfloat16(v0);
                    __nv_bfloat16 h1 = __float2bfloat16(v1);
                    __nv_bfloat162 hh, ll;
                    hh.x = h0; hh.y = h1;
                    ll.x = __float2bfloat16(v0 - __bfloat162float(h0));
                    ll.y = __float2bfloat16(v1 - __bfloat162float(h1));
                    *reinterpret_cast<__nv_bfloat162*>(&outH[(size_t)r * N + n]) = hh;
                    *reinterpret_cast<__nv_bfloat162*>(&outL[(size_t)r * N + n]) = ll;
                } else {
                    float2 o; o.x = v0; o.y = v1;
                    *reinterpret_cast<float2*>(&outF[(size_t)r * N + n]) = o;
                }
            }
        }
    }
}

// ------------------------------ launch -------------------------------------
extern "C" void kernel_launch(void* const* d_in, const int* in_sizes, int n_in,
                              void* d_out, int out_size) {
    const float* x       = (const float*)d_in[0];
    const float* weights = (const float*)d_in[1];
    const float* W0 = (const float*)d_in[2];
    const float* b0 = (const float*)d_in[3];
    const float* a0 = (const float*)d_in[4];
    const float* W1 = (const float*)d_in[5];
    const float* b1 = (const float*)d_in[6];
    const float* a1 = (const float*)d_in[7];
    const float* W2 = (const float*)d_in[8];
    const float* b2 = (const float*)d_in[9];
    const float* a2 = (const float*)d_in[10];
    float* out = (float*)d_out;

    auto sym = [](const void* s) {
        void* p = nullptr;
        cudaGetSymbolAddress(&p, (const void*)s);
        return p;
    };
    __nv_bfloat16* xhi = (__nv_bfloat16*)sym(g_xhi);
    __nv_bfloat16* xlo = (__nv_bfloat16*)sym(g_xlo);
    __nv_bfloat16* h0 = (__nv_bfloat16*)sym(g_h0);
    __nv_bfloat16* l0 = (__nv_bfloat16*)sym(g_l0);
    __nv_bfloat16* h1 = (__nv_bfloat16*)sym(g_h1);
    __nv_bfloat16* l1 = (__nv_bfloat16*)sym(g_l1);
    __nv_bfloat16* wt0h = (__nv_bfloat16*)sym(g_wt0h);
    __nv_bfloat16* wt0l = (__nv_bfloat16*)sym(g_wt0l);
    __nv_bfloat16* wt1h = (__nv_bfloat16*)sym(g_wt1h);
    __nv_bfloat16* wt1l = (__nv_bfloat16*)sym(g_wt1l);
    __nv_bfloat16* wt2h = (__nv_bfloat16*)sym(g_wt2h);
    __nv_bfloat16* wt2l = (__nv_bfloat16*)sym(g_wt2l);
    float* bm0 = (float*)sym(g_bm0);
    float* bm1 = (float*)sym(g_bm1);
    float* bm2 = (float*)sym(g_bm2);

    cudaFuncSetAttribute(gemm_hmma<1>, cudaFuncAttributeMaxDynamicSharedMemorySize, SMEM_DYN);
    cudaFuncSetAttribute(gemm_hmma<0>, cudaFuncAttributeMaxDynamicSharedMemorySize, SMEM_DYN);

    // merge + transpose + split weights
    merge_split_w<<<dim3(512 / 32, 1024 / 32), dim3(32, 8)>>>(weights, W0, b0, wt0h, wt0l, bm0, 512, 1024);
    merge_split_w<<<dim3(1024 / 32, 1024 / 32), dim3(32, 8)>>>(weights, W1, b1, wt1h, wt1l, bm1, 1024, 1024);
    merge_split_w<<<dim3(1024 / 32, 512 / 32), dim3(32, 8)>>>(weights, W2, b2, wt2h, wt2l, bm2, 1024, 512);

    // split input activations to bf16 hi/lo
    split_x<<<(8192 * 512 + 255) / 256, 256>>>(x, xhi, xlo, 8192 * 512);

    // layer 0: [8192,512] @ [512,1024]
    gemm_hmma<1><<<dim3(1024 / 256, M_ROWS / 128), 512, SMEM_DYN>>>(
        xhi, xlo, wt0h, wt0l, bm0, a0, nullptr, h0, l0, M_ROWS, 1024, 512);
    // layer 1: [8192,1024] @ [1024,1024]
    gemm_hmma<1><<<dim3(1024 / 256, M_ROWS / 128), 512, SMEM_DYN>>>(
        h0, l0, wt1h, wt1l, bm1, a1, nullptr, h1, l1, M_ROWS, 1024, 1024);
    // layer 2: [8192,1024] @ [1024,512] -> fp32 out
    gemm_hmma<0><<<dim3(512 / 256, M_ROWS / 128), 512, SMEM_DYN>>>(
        h1, l1, wt2h, wt2l, bm2, a2, out, nullptr, nullptr, M_ROWS, 512, 1024);
}

// round 5
// speedup vs baseline: 2.4615x; 1.0548x over previous
#include <cuda_runtime.h>
#include <cuda_bf16.h>
#include <cstdint>

// ===========================================================================
// mie_51281909514553 — 3-layer expert-merged MLP, bf16-split HMMA (mma.sync)
//   fp32 emulated as bf16 hi+lo: D += Ah*Bh + Ah*Bl + Al*Bh (fp32 accumulate)
// R5: BM=128 BN=128, 256 threads, 2 CTAs/SM (cross-CTA bubble filling),
//     2-stage cp.async pipeline, single sync per chunk.
// ===========================================================================

#define M_ROWS 8192
#define E_EXPERTS 8

// ------------------------------ scratch (no allocs allowed) ----------------
__device__ __nv_bfloat16 g_xhi[8192 * 512];
__device__ __nv_bfloat16 g_xlo[8192 * 512];
__device__ __nv_bfloat16 g_h0[8192 * 1024];
__device__ __nv_bfloat16 g_l0[8192 * 1024];
__device__ __nv_bfloat16 g_h1[8192 * 1024];
__device__ __nv_bfloat16 g_l1[8192 * 1024];
__device__ __nv_bfloat16 g_wt0h[1024 * 512];   // merged W^T: [N][K]
__device__ __nv_bfloat16 g_wt0l[1024 * 512];
__device__ __nv_bfloat16 g_wt1h[1024 * 1024];
__device__ __nv_bfloat16 g_wt1l[1024 * 1024];
__device__ __nv_bfloat16 g_wt2h[512 * 1024];
__device__ __nv_bfloat16 g_wt2l[512 * 1024];
__device__ float g_bm0[1024];
__device__ float g_bm1[1024];
__device__ float g_bm2[512];

// ------------------------------ helpers ------------------------------------
__device__ __forceinline__ uint32_t smem_u32(const void* p) {
    uint32_t a;
    asm("{ .reg .u64 t; cvta.to.shared.u64 t, %1; cvt.u32.u64 %0, t; }"
        : "=r"(a) : "l"(p));
    return a;
}

__device__ __forceinline__ void cp16(uint32_t s, const void* g) {
    asm volatile("cp.async.cg.shared.global [%0], [%1], 16;" :: "r"(s), "l"(g) : "memory");
}
#define CP_COMMIT() asm volatile("cp.async.commit_group;" ::: "memory")
#define CP_WAIT(n)  asm volatile("cp.async.wait_group %0;" :: "n"(n) : "memory")

__device__ __forceinline__ void ldsm4(uint32_t& r0, uint32_t& r1,
                                      uint32_t& r2, uint32_t& r3, uint32_t a) {
    asm volatile("ldmatrix.sync.aligned.m8n8.x4.shared.b16 {%0,%1,%2,%3}, [%4];"
                 : "=r"(r0), "=r"(r1), "=r"(r2), "=r"(r3) : "r"(a));
}

__device__ __forceinline__ void mma_bf16(float* c, const uint32_t* a, const uint32_t* b) {
    asm volatile(
        "mma.sync.aligned.m16n8k16.row.col.f32.bf16.bf16.f32 "
        "{%0,%1,%2,%3}, {%4,%5,%6,%7}, {%8,%9}, {%0,%1,%2,%3};"
        : "+f"(c[0]), "+f"(c[1]), "+f"(c[2]), "+f"(c[3])
        : "r"(a[0]), "r"(a[1]), "r"(a[2]), "r"(a[3]), "r"(b[0]), "r"(b[1]));
}

// ------------------------------ merge+transpose+split ----------------------
__global__ void merge_split_w(const float* __restrict__ weights,
                              const float* __restrict__ W,
                              const float* __restrict__ b,
                              __nv_bfloat16* __restrict__ Th,
                              __nv_bfloat16* __restrict__ Tl,
                              float* __restrict__ bm,
                              int K, int N) {
    __shared__ float tile[32][33];
    float s = 0.f;
#pragma unroll
    for (int e = 0; e < E_EXPERTS; e++) s += weights[e];
    const float inv = 1.f / s;
    float wn[E_EXPERTS];
#pragma unroll
    for (int e = 0; e < E_EXPERTS; e++) wn[e] = weights[e] * inv;

    const int k0 = blockIdx.x * 32, n0 = blockIdx.y * 32;
    for (int ty = threadIdx.y; ty < 32; ty += 8) {
        int k = k0 + ty, n = n0 + threadIdx.x;
        float acc = 0.f;
#pragma unroll
        for (int e = 0; e < E_EXPERTS; e++)
            acc += wn[e] * W[(size_t)e * K * N + (size_t)k * N + n];
        tile[ty][threadIdx.x] = acc;
    }
    if (blockIdx.x == 0 && threadIdx.y == 0) {
        int n = n0 + threadIdx.x;
        float acc = 0.f;
#pragma unroll
        for (int e = 0; e < E_EXPERTS; e++) acc += wn[e] * b[e * N + n];
        bm[n] = acc;
    }
    __syncthreads();
    for (int ty = threadIdx.y; ty < 32; ty += 8) {
        int n = n0 + ty, k = k0 + threadIdx.x;
        float v = tile[threadIdx.x][ty];
        __nv_bfloat16 h = __float2bfloat16(v);
        __nv_bfloat16 l = __float2bfloat16(v - __bfloat162float(h));
        Th[(size_t)n * K + k] = h;
        Tl[(size_t)n * K + k] = l;
    }
}

__global__ void split_x(const float* __restrict__ x,
                        __nv_bfloat16* __restrict__ xh,
                        __nv_bfloat16* __restrict__ xl, int n) {
    int i = blockIdx.x * blockDim.x + threadIdx.x;
    if (i < n) {
        float v = x[i];
        __nv_bfloat16 h = __float2bfloat16(v);
        xh[i] = h;
        xl[i] = __float2bfloat16(v - __bfloat162float(h));
    }
}

// ------------------------------ HMMA GEMM ----------------------------------
// BM=128, BN=128, BK=32, 256 threads (8 warps: 4 along M x 2 along N),
// warp tile 32(m) x 64(n). 2-stage cp.async pipeline, one sync per chunk,
// 2 CTAs per SM. smem row stride 40 bf16 (80B), conflict-free ldmatrix.
#define BK 32
#define STAGES 2
#define TSTRIDE 40
#define ROWB (TSTRIDE * 2)                  // 80 bytes
#define TILE_B (128 * ROWB)                 // 10240 bytes per tile
#define STAGE_B (4 * TILE_B)                // Ah, Al, Bh, Bl = 40960 bytes
#define SMEM_DYN (STAGES * STAGE_B)         // 81920 bytes -> 2 CTAs/SM

template <int OUT_BF16>
__global__ __launch_bounds__(256, 2)
void gemm_hmma(const __nv_bfloat16* __restrict__ Ah, const __nv_bfloat16* __restrict__ Al,
               const __nv_bfloat16* __restrict__ Bh, const __nv_bfloat16* __restrict__ Bl,
               const float* __restrict__ bias, const float* __restrict__ alpha,
               float* __restrict__ outF,
               __nv_bfloat16* __restrict__ outH, __nv_bfloat16* __restrict__ outL,
               int M, int N, int K) {
    extern __shared__ char smem[];
    const uint32_t sbase = smem_u32(smem);

    const int tid = threadIdx.x;
    const int wid = tid >> 5, lane = tid & 31;
    const int gid = lane >> 2, tg = lane & 3;
    const int warp_m = (wid & 3) * 32;      // 0..96
    const int warp_n = (wid >> 2) * 64;     // 0 or 64
    const int block_m = blockIdx.y * 128;
    const int block_n = blockIdx.x * 128;

    // ldmatrix lane byte-offsets within a tile
    uint32_t a_off[2];
#pragma unroll
    for (int mt = 0; mt < 2; mt++)
        a_off[mt] = ((warp_m + mt * 16 + (lane & 15)) * TSTRIDE + (lane >> 4) * 8) * 2;
    uint32_t b_off[4];
#pragma unroll
    for (int nt2 = 0; nt2 < 4; nt2++)
        b_off[nt2] = ((warp_n + nt2 * 16 + (lane >> 4) * 8 + (lane & 7)) * TSTRIDE +
                      ((lane >> 3) & 1) * 8) * 2;

    float acc[2][8][4];
#pragma unroll
    for (int mt = 0; mt < 2; mt++)
#pragma unroll
        for (int nt = 0; nt < 8; nt++)
#pragma unroll
            for (int j = 0; j < 4; j++) acc[mt][nt][j] = 0.f;

    const int nK = K / BK;

    auto stg = [&](int s) { return sbase + (uint32_t)s * STAGE_B; };

    // each tile = 128 rows x 32 cols bf16 = 512 x 16B chunks; 256 threads x 2
    auto load_stage = [&](int ki, int s) {
        const int k0 = ki * BK;
        const uint32_t base = stg(s);
#pragma unroll
        for (int j = 0; j < 2; j++) {
            int chunk = j * 256 + tid;
            int r = chunk >> 2, c = chunk & 3;
            uint32_t so = (uint32_t)(r * ROWB + c * 16);
            const size_t goA = (size_t)(block_m + r) * K + k0 + c * 8;
            const size_t goB = (size_t)(block_n + r) * K + k0 + c * 8;
            cp16(base + so, Ah + goA);
            cp16(base + TILE_B + so, Al + goA);
            cp16(base + 2 * TILE_B + so, Bh + goB);
            cp16(base + 3 * TILE_B + so, Bl + goB);
        }
    };

    // preload chunk 0
    load_stage(0, 0);
    CP_COMMIT();

    for (int i = 0; i < nK; i++) {
        CP_WAIT(0);                 // chunk i resident
        __syncthreads();            // all warps done with chunk i-1's slot

        // prefetch chunk i+1 into the other slot
        if (i + 1 < nK) load_stage(i + 1, (i + 1) & 1);
        CP_COMMIT();

        const uint32_t tAh = stg(i & 1);
        const uint32_t tAl = tAh + TILE_B;
        const uint32_t tBh = tAl + TILE_B;
        const uint32_t tBl = tBh + TILE_B;

#pragma unroll
        for (int ks = 0; ks < 2; ks++) {
            const uint32_t kb = ks * 32;   // 16 bf16 = 32 bytes
            uint32_t ah[2][4], al[2][4];
#pragma unroll
            for (int mt = 0; mt < 2; mt++) {
                ldsm4(ah[mt][0], ah[mt][1], ah[mt][2], ah[mt][3], tAh + a_off[mt] + kb);
                ldsm4(al[mt][0], al[mt][1], al[mt][2], al[mt][3], tAl + a_off[mt] + kb);
            }
#pragma unroll
            for (int nt2 = 0; nt2 < 4; nt2++) {
                uint32_t bh[2][2], bl[2][2];
                ldsm4(bh[0][0], bh[0][1], bh[1][0], bh[1][1], tBh + b_off[nt2] + kb);
                ldsm4(bl[0][0], bl[0][1], bl[1][0], bl[1][1], tBl + b_off[nt2] + kb);
#pragma unroll
                for (int h = 0; h < 2; h++) {
                    const int nt = 2 * nt2 + h;
#pragma unroll
                    for (int mt = 0; mt < 2; mt++) {
                        mma_bf16(acc[mt][nt], ah[mt], bh[h]);
                        mma_bf16(acc[mt][nt], ah[mt], bl[h]);
                        mma_bf16(acc[mt][nt], al[mt], bh[h]);
                    }
                }
            }
        }
    }

    // ---------------- epilogue: bias + PReLU, store straight from regs ------
#pragma unroll
    for (int mt = 0; mt < 2; mt++) {
        const int r0 = block_m + warp_m + mt * 16 + gid;
#pragma unroll
        for (int nt = 0; nt < 8; nt++) {
            const int n = block_n + warp_n + nt * 8 + tg * 2;
            const float b0 = __ldg(&bias[n]),  b1 = __ldg(&bias[n + 1]);
            const float p0 = __ldg(&alpha[n]), p1 = __ldg(&alpha[n + 1]);
#pragma unroll
            for (int half = 0; half < 2; half++) {
                const int r = r0 + half * 8;
                float v0 = acc[mt][nt][half * 2 + 0] + b0;
                float v1 = acc[mt][nt][half * 2 + 1] + b1;
                v0 = v0 >= 0.f ? v0 : p0 * v0;
                v1 = v1 >= 0.f ? v1 : p1 * v1;
                if (OUT_BF16) {
                    __nv_bfloat16 h0 = __float2bfloat16(v0);
                    __nv_bfloat16 h1 = __float2bfloat16(v1);
                    __nv_bfloat162 hh, ll;
                    hh.x = h0; hh.y = h1;
                    ll.x = __float2bfloat16(v0 - __bfloat162float(h0));
                    ll.y = __float2bfloat16(v1 - __bfloat162float(h1));
                    *reinterpret_cast<__nv_bfloat162*>(&outH[(size_t)r * N + n]) = hh;
                    *reinterpret_cast<__nv_bfloat162*>(&outL[(size_t)r * N + n]) = ll;
                } else {
                    float2 o; o.x = v0; o.y = v1;
                    *reinterpret_cast<float2*>(&outF[(size_t)r * N + n]) = o;
                }
            }
        }
    }
}

// ------------------------------ launch -------------------------------------
extern "C" void kernel_launch(void* const* d_in, const int* in_sizes, int n_in,
                              void* d_out, int out_size) {
    const float* x       = (const float*)d_in[0];
    const float* weights = (const float*)d_in[1];
    const float* W0 = (const float*)d_in[2];
    const float* b0 = (const float*)d_in[3];
    const float* a0 = (const float*)d_in[4];
    const float* W1 = (const float*)d_in[5];
    const float* b1 = (const float*)d_in[6];
    const float* a1 = (const float*)d_in[7];
    const float* W2 = (const float*)d_in[8];
    const float* b2 = (const float*)d_in[9];
    const float* a2 = (const float*)d_in[10];
    float* out = (float*)d_out;

    auto sym = [](const void* s) {
        void* p = nullptr;
        cudaGetSymbolAddress(&p, (const void*)s);
        return p;
    };
    __nv_bfloat16* xhi = (__nv_bfloat16*)sym(g_xhi);
    __nv_bfloat16* xlo = (__nv_bfloat16*)sym(g_xlo);
    __nv_bfloat16* h0 = (__nv_bfloat16*)sym(g_h0);
    __nv_bfloat16* l0 = (__nv_bfloat16*)sym(g_l0);
    __nv_bfloat16* h1 = (__nv_bfloat16*)sym(g_h1);
    __nv_bfloat16* l1 = (__nv_bfloat16*)sym(g_l1);
    __nv_bfloat16* wt0h = (__nv_bfloat16*)sym(g_wt0h);
    __nv_bfloat16* wt0l = (__nv_bfloat16*)sym(g_wt0l);
    __nv_bfloat16* wt1h = (__nv_bfloat16*)sym(g_wt1h);
    __nv_bfloat16* wt1l = (__nv_bfloat16*)sym(g_wt1l);
    __nv_bfloat16* wt2h = (__nv_bfloat16*)sym(g_wt2h);
    __nv_bfloat16* wt2l = (__nv_bfloat16*)sym(g_wt2l);
    float* bm0 = (float*)sym(g_bm0);
    float* bm1 = (float*)sym(g_bm1);
    float* bm2 = (float*)sym(g_bm2);

    cudaFuncSetAttribute(gemm_hmma<1>, cudaFuncAttributeMaxDynamicSharedMemorySize, SMEM_DYN);
    cudaFuncSetAttribute(gemm_hmma<0>, cudaFuncAttributeMaxDynamicSharedMemorySize, SMEM_DYN);

    // merge + transpose + split weights
    merge_split_w<<<dim3(512 / 32, 1024 / 32), dim3(32, 8)>>>(weights, W0, b0, wt0h, wt0l, bm0, 512, 1024);
    merge_split_w<<<dim3(1024 / 32, 1024 / 32), dim3(32, 8)>>>(weights, W1, b1, wt1h, wt1l, bm1, 1024, 1024);
    merge_split_w<<<dim3(1024 / 32, 512 / 32), dim3(32, 8)>>>(weights, W2, b2, wt2h, wt2l, bm2, 1024, 512);

    // split input activations to bf16 hi/lo
    split_x<<<(8192 * 512 + 255) / 256, 256>>>(x, xhi, xlo, 8192 * 512);

    // layer 0: [8192,512] @ [512,1024]
    gemm_hmma<1><<<dim3(1024 / 128, M_ROWS / 128), 256, SMEM_DYN>>>(
        xhi, xlo, wt0h, wt0l, bm0, a0, nullptr, h0, l0, M_ROWS, 1024, 512);
    // layer 1: [8192,1024] @ [1024,1024]
    gemm_hmma<1><<<dim3(1024 / 128, M_ROWS / 128), 256, SMEM_DYN>>>(
        h0, l0, wt1h, wt1l, bm1, a1, nullptr, h1, l1, M_ROWS, 1024, 1024);
    // layer 2: [8192,1024] @ [1024,512] -> fp32 out
    gemm_hmma<0><<<dim3(512 / 128, M_ROWS / 128), 256, SMEM_DYN>>>(
        h1, l1, wt2h, wt2l, bm2, a2, out, nullptr, nullptr, M_ROWS, 512, 1024);
}

// round 6
// speedup vs baseline: 3.2783x; 1.3318x over previous
#include <cuda_runtime.h>
#include <cuda_fp16.h>
#include <cstdint>

// ===========================================================================
// mie_51281909514553 — 3-layer expert-merged MLP, fp16 2-term HMMA
//   wn = weights/sum(weights); per layer: x = PReLU(x @ Wm + bm, a)
//   Weights kept exact as fp16 hi+lo (Wm = Bh + Bl to ~2^-19);
//   activations carried as single fp16 plane (error ~1.4e-4/layer L2).
//   D = A*Bh + A*Bl, fp32 accumulate. 2 MMAs per tile-pair (was 3).
// ===========================================================================

#define M_ROWS 8192
#define E_EXPERTS 8

// ------------------------------ scratch (no allocs allowed) ----------------
__device__ __half g_xh[8192 * 1024];       // layer input activations (fp16)
__device__ __half g_a0[8192 * 1024];
__device__ __half g_wt0h[1024 * 512];      // merged W^T hi: [N][K]
__device__ __half g_wt0l[1024 * 512];      // merged W^T lo
__device__ __half g_wt1h[1024 * 1024];
__device__ __half g_wt1l[1024 * 1024];
__device__ __half g_wt2h[512 * 1024];
__device__ __half g_wt2l[512 * 1024];
__device__ float g_bm0[1024];
__device__ float g_bm1[1024];
__device__ float g_bm2[512];

// ------------------------------ helpers ------------------------------------
__device__ __forceinline__ uint32_t smem_u32(const void* p) {
    uint32_t a;
    asm("{ .reg .u64 t; cvta.to.shared.u64 t, %1; cvt.u32.u64 %0, t; }"
        : "=r"(a) : "l"(p));
    return a;
}

__device__ __forceinline__ void cp16(uint32_t s, const void* g) {
    asm volatile("cp.async.cg.shared.global [%0], [%1], 16;" :: "r"(s), "l"(g) : "memory");
}
#define CP_COMMIT() asm volatile("cp.async.commit_group;" ::: "memory")
#define CP_WAIT(n)  asm volatile("cp.async.wait_group %0;" :: "n"(n) : "memory")

__device__ __forceinline__ void ldsm4(uint32_t& r0, uint32_t& r1,
                                      uint32_t& r2, uint32_t& r3, uint32_t a) {
    asm volatile("ldmatrix.sync.aligned.m8n8.x4.shared.b16 {%0,%1,%2,%3}, [%4];"
                 : "=r"(r0), "=r"(r1), "=r"(r2), "=r"(r3) : "r"(a));
}

__device__ __forceinline__ void mma_f16(float* c, const uint32_t* a, const uint32_t* b) {
    asm volatile(
        "mma.sync.aligned.m16n8k16.row.col.f32.f16.f16.f32 "
        "{%0,%1,%2,%3}, {%4,%5,%6,%7}, {%8,%9}, {%0,%1,%2,%3};"
        : "+f"(c[0]), "+f"(c[1]), "+f"(c[2]), "+f"(c[3])
        : "r"(a[0]), "r"(a[1]), "r"(a[2]), "r"(a[3]), "r"(b[0]), "r"(b[1]));
}

// ------------------------------ merge+transpose+split ----------------------
// Wm^T[n][k] = sum_e wn_e W[e][k][n] -> fp16 hi/lo planes; bm[n] merged bias.
__global__ void merge_split_w(const float* __restrict__ weights,
                              const float* __restrict__ W,
                              const float* __restrict__ b,
                              __half* __restrict__ Th,
                              __half* __restrict__ Tl,
                              float* __restrict__ bm,
                              int K, int N) {
    __shared__ float tile[32][33];
    float s = 0.f;
#pragma unroll
    for (int e = 0; e < E_EXPERTS; e++) s += weights[e];
    const float inv = 1.f / s;
    float wn[E_EXPERTS];
#pragma unroll
    for (int e = 0; e < E_EXPERTS; e++) wn[e] = weights[e] * inv;

    const int k0 = blockIdx.x * 32, n0 = blockIdx.y * 32;
    for (int ty = threadIdx.y; ty < 32; ty += 8) {
        int k = k0 + ty, n = n0 + threadIdx.x;
        float acc = 0.f;
#pragma unroll
        for (int e = 0; e < E_EXPERTS; e++)
            acc += wn[e] * W[(size_t)e * K * N + (size_t)k * N + n];
        tile[ty][threadIdx.x] = acc;
    }
    if (blockIdx.x == 0 && threadIdx.y == 0) {
        int n = n0 + threadIdx.x;
        float acc = 0.f;
#pragma unroll
        for (int e = 0; e < E_EXPERTS; e++) acc += wn[e] * b[e * N + n];
        bm[n] = acc;
    }
    __syncthreads();
    for (int ty = threadIdx.y; ty < 32; ty += 8) {
        int n = n0 + ty, k = k0 + threadIdx.x;
        float v = tile[threadIdx.x][ty];
        __half h = __float2half_rn(v);
        __half l = __float2half_rn(v - __half2float(h));
        Th[(size_t)n * K + k] = h;
        Tl[(size_t)n * K + k] = l;
    }
}

// fp32 -> fp16 for layer-0 input
__global__ void cast_x(const float* __restrict__ x, __half* __restrict__ xh, int n) {
    int i = blockIdx.x * blockDim.x + threadIdx.x;
    if (i < n) xh[i] = __float2half_rn(x[i]);
}

// ------------------------------ HMMA GEMM ----------------------------------
// BM=128, BN=128, BK=32, 256 threads (8 warps: 4 M x 2 N), warp tile 32x64.
// 2-stage cp.async pipeline, one sync per chunk, 2 CTAs per SM.
// smem tiles: A, Bh, Bl; row stride 40 fp16 (80B), conflict-free ldmatrix.
#define BK 32
#define TSTRIDE 40
#define ROWB (TSTRIDE * 2)                  // 80 bytes
#define TILE_B (128 * ROWB)                 // 10240 bytes per tile
#define STAGE_B (3 * TILE_B)                // A, Bh, Bl = 30720 bytes
#define SMEM_DYN (2 * STAGE_B)              // 61440 bytes -> 2 CTAs/SM

template <int OUT_HALF>
__global__ __launch_bounds__(256, 2)
void gemm_hmma(const __half* __restrict__ A,
               const __half* __restrict__ Bh, const __half* __restrict__ Bl,
               const float* __restrict__ bias, const float* __restrict__ alpha,
               float* __restrict__ outF, __half* __restrict__ outH,
               int M, int N, int K) {
    extern __shared__ char smem[];
    const uint32_t sbase = smem_u32(smem);

    const int tid = threadIdx.x;
    const int wid = tid >> 5, lane = tid & 31;
    const int gid = lane >> 2, tg = lane & 3;
    const int warp_m = (wid & 3) * 32;      // 0..96
    const int warp_n = (wid >> 2) * 64;     // 0 or 64
    const int block_m = blockIdx.y * 128;
    const int block_n = blockIdx.x * 128;

    // ldmatrix lane byte-offsets within a tile
    uint32_t a_off[2];
#pragma unroll
    for (int mt = 0; mt < 2; mt++)
        a_off[mt] = ((warp_m + mt * 16 + (lane & 15)) * TSTRIDE + (lane >> 4) * 8) * 2;
    uint32_t b_off[4];
#pragma unroll
    for (int nt2 = 0; nt2 < 4; nt2++)
        b_off[nt2] = ((warp_n + nt2 * 16 + (lane >> 4) * 8 + (lane & 7)) * TSTRIDE +
                      ((lane >> 3) & 1) * 8) * 2;

    float acc[2][8][4];
#pragma unroll
    for (int mt = 0; mt < 2; mt++)
#pragma unroll
        for (int nt = 0; nt < 8; nt++)
#pragma unroll
            for (int j = 0; j < 4; j++) acc[mt][nt][j] = 0.f;

    const int nK = K / BK;
    auto stg = [&](int s) { return sbase + (uint32_t)s * STAGE_B; };

    // each tile = 128 rows x 32 cols fp16 = 512 x 16B chunks; 256 threads x 2
    auto load_stage = [&](int ki, int s) {
        const int k0 = ki * BK;
        const uint32_t base = stg(s);
#pragma unroll
        for (int j = 0; j < 2; j++) {
            int chunk = j * 256 + tid;
            int r = chunk >> 2, c = chunk & 3;
            uint32_t so = (uint32_t)(r * ROWB + c * 16);
            const size_t goA = (size_t)(block_m + r) * K + k0 + c * 8;
            const size_t goB = (size_t)(block_n + r) * K + k0 + c * 8;
            cp16(base + so, A + goA);
            cp16(base + TILE_B + so, Bh + goB);
            cp16(base + 2 * TILE_B + so, Bl + goB);
        }
    };

    load_stage(0, 0);
    CP_COMMIT();

    for (int i = 0; i < nK; i++) {
        CP_WAIT(0);
        __syncthreads();

        if (i + 1 < nK) load_stage(i + 1, (i + 1) & 1);
        CP_COMMIT();

        const uint32_t tA = stg(i & 1);
        const uint32_t tBh = tA + TILE_B;
        const uint32_t tBl = tBh + TILE_B;

#pragma unroll
        for (int ks = 0; ks < 2; ks++) {
            const uint32_t kb = ks * 32;   // 16 fp16 = 32 bytes
            uint32_t af[2][4];
#pragma unroll
            for (int mt = 0; mt < 2; mt++)
                ldsm4(af[mt][0], af[mt][1], af[mt][2], af[mt][3], tA + a_off[mt] + kb);
#pragma unroll
            for (int nt2 = 0; nt2 < 4; nt2++) {
                uint32_t bh[2][2], bl[2][2];
                ldsm4(bh[0][0], bh[0][1], bh[1][0], bh[1][1], tBh + b_off[nt2] + kb);
                ldsm4(bl[0][0], bl[0][1], bl[1][0], bl[1][1], tBl + b_off[nt2] + kb);
#pragma unroll
                for (int h = 0; h < 2; h++) {
                    const int nt = 2 * nt2 + h;
#pragma unroll
                    for (int mt = 0; mt < 2; mt++) {
                        mma_f16(acc[mt][nt], af[mt], bh[h]);
                        mma_f16(acc[mt][nt], af[mt], bl[h]);
                    }
                }
            }
        }
    }

    // ---------------- epilogue: bias + PReLU, store straight from regs ------
#pragma unroll
    for (int mt = 0; mt < 2; mt++) {
        const int r0 = block_m + warp_m + mt * 16 + gid;
#pragma unroll
        for (int nt = 0; nt < 8; nt++) {
            const int n = block_n + warp_n + nt * 8 + tg * 2;
            const float b0 = __ldg(&bias[n]),  b1 = __ldg(&bias[n + 1]);
            const float p0 = __ldg(&alpha[n]), p1 = __ldg(&alpha[n + 1]);
#pragma unroll
            for (int half = 0; half < 2; half++) {
                const int r = r0 + half * 8;
                float v0 = acc[mt][nt][half * 2 + 0] + b0;
                float v1 = acc[mt][nt][half * 2 + 1] + b1;
                v0 = v0 >= 0.f ? v0 : p0 * v0;
                v1 = v1 >= 0.f ? v1 : p1 * v1;
                if (OUT_HALF) {
                    __half2 hh;
                    hh.x = __float2half_rn(v0);
                    hh.y = __float2half_rn(v1);
                    *reinterpret_cast<__half2*>(&outH[(size_t)r * N + n]) = hh;
                } else {
                    float2 o; o.x = v0; o.y = v1;
                    *reinterpret_cast<float2*>(&outF[(size_t)r * N + n]) = o;
                }
            }
        }
    }
}

// ------------------------------ launch -------------------------------------
extern "C" void kernel_launch(void* const* d_in, const int* in_sizes, int n_in,
                              void* d_out, int out_size) {
    const float* x       = (const float*)d_in[0];
    const float* weights = (const float*)d_in[1];
    const float* W0 = (const float*)d_in[2];
    const float* b0 = (const float*)d_in[3];
    const float* a0 = (const float*)d_in[4];
    const float* W1 = (const float*)d_in[5];
    const float* b1 = (const float*)d_in[6];
    const float* a1 = (const float*)d_in[7];
    const float* W2 = (const float*)d_in[8];
    const float* b2 = (const float*)d_in[9];
    const float* a2 = (const float*)d_in[10];
    float* out = (float*)d_out;

    auto sym = [](const void* s) {
        void* p = nullptr;
        cudaGetSymbolAddress(&p, (const void*)s);
        return p;
    };
    __half* xh  = (__half*)sym(g_xh);
    __half* act0 = (__half*)sym(g_a0);
    __half* wt0h = (__half*)sym(g_wt0h);
    __half* wt0l = (__half*)sym(g_wt0l);
    __half* wt1h = (__half*)sym(g_wt1h);
    __half* wt1l = (__half*)sym(g_wt1l);
    __half* wt2h = (__half*)sym(g_wt2h);
    __half* wt2l = (__half*)sym(g_wt2l);
    float* bm0 = (float*)sym(g_bm0);
    float* bm1 = (float*)sym(g_bm1);
    float* bm2 = (float*)sym(g_bm2);

    cudaFuncSetAttribute(gemm_hmma<1>, cudaFuncAttributeMaxDynamicSharedMemorySize, SMEM_DYN);
    cudaFuncSetAttribute(gemm_hmma<0>, cudaFuncAttributeMaxDynamicSharedMemorySize, SMEM_DYN);

    // merge + transpose + split weights (fp16 hi/lo)
    merge_split_w<<<dim3(512 / 32, 1024 / 32), dim3(32, 8)>>>(weights, W0, b0, wt0h, wt0l, bm0, 512, 1024);
    merge_split_w<<<dim3(1024 / 32, 1024 / 32), dim3(32, 8)>>>(weights, W1, b1, wt1h, wt1l, bm1, 1024, 1024);
    merge_split_w<<<dim3(1024 / 32, 512 / 32), dim3(32, 8)>>>(weights, W2, b2, wt2h, wt2l, bm2, 1024, 512);

    // cast input activations to fp16
    cast_x<<<(8192 * 512 + 255) / 256, 256>>>(x, xh, 8192 * 512);

    // layer 0: [8192,512] @ [512,1024] -> fp16 act
    gemm_hmma<1><<<dim3(1024 / 128, M_ROWS / 128), 256, SMEM_DYN>>>(
        xh, wt0h, wt0l, bm0, a0, nullptr, act0, M_ROWS, 1024, 512);
    // layer 1: [8192,1024] @ [1024,1024] -> fp16 act (reuse xh buffer)
    gemm_hmma<1><<<dim3(1024 / 128, M_ROWS / 128), 256, SMEM_DYN>>>(
        act0, wt1h, wt1l, bm1, a1, nullptr, xh, M_ROWS, 1024, 1024);
    // layer 2: [8192,1024] @ [1024,512] -> fp32 out
    gemm_hmma<0><<<dim3(512 / 128, M_ROWS / 128), 256, SMEM_DYN>>>(
        xh, wt2h, wt2l, bm2, a2, out, nullptr, M_ROWS, 512, 1024);
}

// round 7
// speedup vs baseline: 5.2474x; 1.6006x over previous
#include <cuda_runtime.h>
#include <cuda_fp16.h>
#include <cstdint>

// ===========================================================================
// mie_51281909514553 — 3-layer expert-merged MLP, pure fp16 HMMA
//   wn = weights/sum(weights); per layer: x = PReLU(x @ Wm + bm, a)
//   Weights + activations fp16 (RN), fp32 accumulate. 1 MMA per tile.
//   mma.sync f32-acc ceiling on sm_103a = 512 MAC/cyc/SM (measured R5/R6);
//   halving HMMA count is the only remaining lever.
// ===========================================================================

#define M_ROWS 8192
#define E_EXPERTS 8

// ------------------------------ scratch (no allocs allowed) ----------------
__device__ __half g_xh[8192 * 1024];       // layer input activations (fp16)
__device__ __half g_a0[8192 * 1024];
__device__ __half g_wt0[1024 * 512];       // merged W^T: [N][K] fp16
__device__ __half g_wt1[1024 * 1024];
__device__ __half g_wt2[512 * 1024];
__device__ float g_bm0[1024];
__device__ float g_bm1[1024];
__device__ float g_bm2[512];

// ------------------------------ helpers ------------------------------------
__device__ __forceinline__ uint32_t smem_u32(const void* p) {
    uint32_t a;
    asm("{ .reg .u64 t; cvta.to.shared.u64 t, %1; cvt.u32.u64 %0, t; }"
        : "=r"(a) : "l"(p));
    return a;
}

__device__ __forceinline__ void cp16(uint32_t s, const void* g) {
    asm volatile("cp.async.cg.shared.global [%0], [%1], 16;" :: "r"(s), "l"(g) : "memory");
}
#define CP_COMMIT() asm volatile("cp.async.commit_group;" ::: "memory")
#define CP_WAIT(n)  asm volatile("cp.async.wait_group %0;" :: "n"(n) : "memory")

__device__ __forceinline__ void ldsm4(uint32_t& r0, uint32_t& r1,
                                      uint32_t& r2, uint32_t& r3, uint32_t a) {
    asm volatile("ldmatrix.sync.aligned.m8n8.x4.shared.b16 {%0,%1,%2,%3}, [%4];"
                 : "=r"(r0), "=r"(r1), "=r"(r2), "=r"(r3) : "r"(a));
}

__device__ __forceinline__ void mma_f16(float* c, const uint32_t* a, const uint32_t* b) {
    asm volatile(
        "mma.sync.aligned.m16n8k16.row.col.f32.f16.f16.f32 "
        "{%0,%1,%2,%3}, {%4,%5,%6,%7}, {%8,%9}, {%0,%1,%2,%3};"
        : "+f"(c[0]), "+f"(c[1]), "+f"(c[2]), "+f"(c[3])
        : "r"(a[0]), "r"(a[1]), "r"(a[2]), "r"(a[3]), "r"(b[0]), "r"(b[1]));
}

// ------------------------------ merge+transpose ----------------------------
// Wm^T[n][k] = sum_e wn_e W[e][k][n] -> fp16; bm[n] merged bias (fp32).
__global__ void merge_w(const float* __restrict__ weights,
                        const float* __restrict__ W,
                        const float* __restrict__ b,
                        __half* __restrict__ T,
                        float* __restrict__ bm,
                        int K, int N) {
    __shared__ float tile[32][33];
    float s = 0.f;
#pragma unroll
    for (int e = 0; e < E_EXPERTS; e++) s += weights[e];
    const float inv = 1.f / s;
    float wn[E_EXPERTS];
#pragma unroll
    for (int e = 0; e < E_EXPERTS; e++) wn[e] = weights[e] * inv;

    const int k0 = blockIdx.x * 32, n0 = blockIdx.y * 32;
    for (int ty = threadIdx.y; ty < 32; ty += 8) {
        int k = k0 + ty, n = n0 + threadIdx.x;
        float acc = 0.f;
#pragma unroll
        for (int e = 0; e < E_EXPERTS; e++)
            acc += wn[e] * W[(size_t)e * K * N + (size_t)k * N + n];
        tile[ty][threadIdx.x] = acc;
    }
    if (blockIdx.x == 0 && threadIdx.y == 0) {
        int n = n0 + threadIdx.x;
        float acc = 0.f;
#pragma unroll
        for (int e = 0; e < E_EXPERTS; e++) acc += wn[e] * b[e * N + n];
        bm[n] = acc;
    }
    __syncthreads();
    for (int ty = threadIdx.y; ty < 32; ty += 8) {
        int n = n0 + ty, k = k0 + threadIdx.x;
        T[(size_t)n * K + k] = __float2half_rn(tile[threadIdx.x][ty]);
    }
}

// fp32 -> fp16, vectorized (float4 in, half2x2 out)
__global__ void cast_x(const float4* __restrict__ x, __half2* __restrict__ xh, int n4) {
    int i = blockIdx.x * blockDim.x + threadIdx.x;
    if (i < n4) {
        float4 v = x[i];
        __half2 a, b;
        a.x = __float2half_rn(v.x); a.y = __float2half_rn(v.y);
        b.x = __float2half_rn(v.z); b.y = __float2half_rn(v.w);
        xh[2 * i] = a;
        xh[2 * i + 1] = b;
    }
}

// ------------------------------ HMMA GEMM ----------------------------------
// BM=128, BN=128, BK=32, 256 threads (8 warps: 4 M x 2 N), warp tile 32x64.
// 2-stage cp.async pipeline, one sync per chunk, 2 CTAs per SM.
// smem tiles: A, B; row stride 40 fp16 (80B), conflict-free ldmatrix.
#define BK 32
#define TSTRIDE 40
#define ROWB (TSTRIDE * 2)                  // 80 bytes
#define TILE_B (128 * ROWB)                 // 10240 bytes per tile
#define STAGE_B (2 * TILE_B)                // A, B = 20480 bytes
#define SMEM_DYN (2 * STAGE_B)              // 40960 bytes -> 2 CTAs/SM

template <int OUT_HALF>
__global__ __launch_bounds__(256, 2)
void gemm_hmma(const __half* __restrict__ A, const __half* __restrict__ B,
               const float* __restrict__ bias, const float* __restrict__ alpha,
               float* __restrict__ outF, __half* __restrict__ outH,
               int M, int N, int K) {
    extern __shared__ char smem[];
    const uint32_t sbase = smem_u32(smem);

    const int tid = threadIdx.x;
    const int wid = tid >> 5, lane = tid & 31;
    const int gid = lane >> 2, tg = lane & 3;
    const int warp_m = (wid & 3) * 32;      // 0..96
    const int warp_n = (wid >> 2) * 64;     // 0 or 64
    const int block_m = blockIdx.y * 128;
    const int block_n = blockIdx.x * 128;

    // ldmatrix lane byte-offsets within a tile
    uint32_t a_off[2];
#pragma unroll
    for (int mt = 0; mt < 2; mt++)
        a_off[mt] = ((warp_m + mt * 16 + (lane & 15)) * TSTRIDE + (lane >> 4) * 8) * 2;
    uint32_t b_off[4];
#pragma unroll
    for (int nt2 = 0; nt2 < 4; nt2++)
        b_off[nt2] = ((warp_n + nt2 * 16 + (lane >> 4) * 8 + (lane & 7)) * TSTRIDE +
                      ((lane >> 3) & 1) * 8) * 2;

    float acc[2][8][4];
#pragma unroll
    for (int mt = 0; mt < 2; mt++)
#pragma unroll
        for (int nt = 0; nt < 8; nt++)
#pragma unroll
            for (int j = 0; j < 4; j++) acc[mt][nt][j] = 0.f;

    const int nK = K / BK;
    auto stg = [&](int s) { return sbase + (uint32_t)s * STAGE_B; };

    // each tile = 128 rows x 32 cols fp16 = 512 x 16B chunks; 256 threads x 2
    auto load_stage = [&](int ki, int s) {
        const int k0 = ki * BK;
        const uint32_t base = stg(s);
#pragma unroll
        for (int j = 0; j < 2; j++) {
            int chunk = j * 256 + tid;
            int r = chunk >> 2, c = chunk & 3;
            uint32_t so = (uint32_t)(r * ROWB + c * 16);
            cp16(base + so, A + (size_t)(block_m + r) * K + k0 + c * 8);
            cp16(base + TILE_B + so, B + (size_t)(block_n + r) * K + k0 + c * 8);
        }
    };

    load_stage(0, 0);
    CP_COMMIT();

    for (int i = 0; i < nK; i++) {
        CP_WAIT(0);
        __syncthreads();

        if (i + 1 < nK) load_stage(i + 1, (i + 1) & 1);
        CP_COMMIT();

        const uint32_t tA = stg(i & 1);
        const uint32_t tB = tA + TILE_B;

#pragma unroll
        for (int ks = 0; ks < 2; ks++) {
            const uint32_t kb = ks * 32;   // 16 fp16 = 32 bytes
            uint32_t af[2][4];
#pragma unroll
            for (int mt = 0; mt < 2; mt++)
                ldsm4(af[mt][0], af[mt][1], af[mt][2], af[mt][3], tA + a_off[mt] + kb);
#pragma unroll
            for (int nt2 = 0; nt2 < 4; nt2++) {
                uint32_t bf[2][2];
                ldsm4(bf[0][0], bf[0][1], bf[1][0], bf[1][1], tB + b_off[nt2] + kb);
#pragma unroll
                for (int h = 0; h < 2; h++) {
                    const int nt = 2 * nt2 + h;
#pragma unroll
                    for (int mt = 0; mt < 2; mt++)
                        mma_f16(acc[mt][nt], af[mt], bf[h]);
                }
            }
        }
    }

    // ---------------- epilogue: bias + PReLU, store straight from regs ------
#pragma unroll
    for (int mt = 0; mt < 2; mt++) {
        const int r0 = block_m + warp_m + mt * 16 + gid;
#pragma unroll
        for (int nt = 0; nt < 8; nt++) {
            const int n = block_n + warp_n + nt * 8 + tg * 2;
            const float b0 = __ldg(&bias[n]),  b1 = __ldg(&bias[n + 1]);
            const float p0 = __ldg(&alpha[n]), p1 = __ldg(&alpha[n + 1]);
#pragma unroll
            for (int half = 0; half < 2; half++) {
                const int r = r0 + half * 8;
                float v0 = acc[mt][nt][half * 2 + 0] + b0;
                float v1 = acc[mt][nt][half * 2 + 1] + b1;
                v0 = v0 >= 0.f ? v0 : p0 * v0;
                v1 = v1 >= 0.f ? v1 : p1 * v1;
                if (OUT_HALF) {
                    __half2 hh;
                    hh.x = __float2half_rn(v0);
                    hh.y = __float2half_rn(v1);
                    *reinterpret_cast<__half2*>(&outH[(size_t)r * N + n]) = hh;
                } else {
                    float2 o; o.x = v0; o.y = v1;
                    *reinterpret_cast<float2*>(&outF[(size_t)r * N + n]) = o;
                }
            }
        }
    }
}

// ------------------------------ launch -------------------------------------
extern "C" void kernel_launch(void* const* d_in, const int* in_sizes, int n_in,
                              void* d_out, int out_size) {
    const float* x       = (const float*)d_in[0];
    const float* weights = (const float*)d_in[1];
    const float* W0 = (const float*)d_in[2];
    const float* b0 = (const float*)d_in[3];
    const float* a0 = (const float*)d_in[4];
    const float* W1 = (const float*)d_in[5];
    const float* b1 = (const float*)d_in[6];
    const float* a1 = (const float*)d_in[7];
    const float* W2 = (const float*)d_in[8];
    const float* b2 = (const float*)d_in[9];
    const float* a2 = (const float*)d_in[10];
    float* out = (float*)d_out;

    auto sym = [](const void* s) {
        void* p = nullptr;
        cudaGetSymbolAddress(&p, (const void*)s);
        return p;
    };
    __half* xh   = (__half*)sym(g_xh);
    __half* act0 = (__half*)sym(g_a0);
    __half* wt0  = (__half*)sym(g_wt0);
    __half* wt1  = (__half*)sym(g_wt1);
    __half* wt2  = (__half*)sym(g_wt2);
    float* bm0 = (float*)sym(g_bm0);
    float* bm1 = (float*)sym(g_bm1);
    float* bm2 = (float*)sym(g_bm2);

    cudaFuncSetAttribute(gemm_hmma<1>, cudaFuncAttributeMaxDynamicSharedMemorySize, SMEM_DYN);
    cudaFuncSetAttribute(gemm_hmma<0>, cudaFuncAttributeMaxDynamicSharedMemorySize, SMEM_DYN);

    // merge + transpose weights -> fp16
    merge_w<<<dim3(512 / 32, 1024 / 32), dim3(32, 8)>>>(weights, W0, b0, wt0, bm0, 512, 1024);
    merge_w<<<dim3(1024 / 32, 1024 / 32), dim3(32, 8)>>>(weights, W1, b1, wt1, bm1, 1024, 1024);
    merge_w<<<dim3(1024 / 32, 512 / 32), dim3(32, 8)>>>(weights, W2, b2, wt2, bm2, 1024, 512);

    // cast input activations to fp16 (vectorized)
    cast_x<<<(8192 * 512 / 4 + 255) / 256, 256>>>(
        (const float4*)x, (__half2*)xh, 8192 * 512 / 4);

    // layer 0: [8192,512] @ [512,1024] -> fp16 act
    gemm_hmma<1><<<dim3(1024 / 128, M_ROWS / 128), 256, SMEM_DYN>>>(
        xh, wt0, bm0, a0, nullptr, act0, M_ROWS, 1024, 512);
    // layer 1: [8192,1024] @ [1024,1024] -> fp16 act (reuse xh)
    gemm_hmma<1><<<dim3(1024 / 128, M_ROWS / 128), 256, SMEM_DYN>>>(
        act0, wt1, bm1, a1, nullptr, xh, M_ROWS, 1024, 1024);
    // layer 2: [8192,1024] @ [1024,512] -> fp32 out
    gemm_hmma<0><<<dim3(512 / 128, M_ROWS / 128), 256, SMEM_DYN>>>(
        xh, wt2, bm2, a2, out, nullptr, M_ROWS, 512, 1024);
}

// round 8
// speedup vs baseline: 5.6931x; 1.0849x over previous
#include <cuda_runtime.h>
#include <cuda_fp16.h>
#include <cstdint>

// ===========================================================================
// mie_51281909514553 — 3-layer expert-merged MLP, pure fp16 HMMA
//   wn = weights/sum(weights); per layer: x = PReLU(x @ Wm + bm, a)
//   Weights + activations fp16 (RN), fp32 accumulate (HMMA ceiling:
//   512 MAC/cyc/SM measured). R8: overlap weight-merge prep (layers 1,2)
//   with GEMMs 0,1 on a forked capture stream.
// ===========================================================================

#define M_ROWS 8192
#define E_EXPERTS 8

// ------------------------------ scratch (no allocs allowed) ----------------
__device__ __half g_xh[8192 * 1024];       // layer input activations (fp16)
__device__ __half g_a0[8192 * 1024];
__device__ __half g_wt0[1024 * 512];       // merged W^T: [N][K] fp16
__device__ __half g_wt1[1024 * 1024];
__device__ __half g_wt2[512 * 1024];
__device__ float g_bm0[1024];
__device__ float g_bm1[1024];
__device__ float g_bm2[512];

// ------------------------------ helpers ------------------------------------
__device__ __forceinline__ uint32_t smem_u32(const void* p) {
    uint32_t a;
    asm("{ .reg .u64 t; cvta.to.shared.u64 t, %1; cvt.u32.u64 %0, t; }"
        : "=r"(a) : "l"(p));
    return a;
}

__device__ __forceinline__ void cp16(uint32_t s, const void* g) {
    asm volatile("cp.async.cg.shared.global [%0], [%1], 16;" :: "r"(s), "l"(g) : "memory");
}
#define CP_COMMIT() asm volatile("cp.async.commit_group;" ::: "memory")
#define CP_WAIT(n)  asm volatile("cp.async.wait_group %0;" :: "n"(n) : "memory")

__device__ __forceinline__ void ldsm4(uint32_t& r0, uint32_t& r1,
                                      uint32_t& r2, uint32_t& r3, uint32_t a) {
    asm volatile("ldmatrix.sync.aligned.m8n8.x4.shared.b16 {%0,%1,%2,%3}, [%4];"
                 : "=r"(r0), "=r"(r1), "=r"(r2), "=r"(r3) : "r"(a));
}

__device__ __forceinline__ void mma_f16(float* c, const uint32_t* a, const uint32_t* b) {
    asm volatile(
        "mma.sync.aligned.m16n8k16.row.col.f32.f16.f16.f32 "
        "{%0,%1,%2,%3}, {%4,%5,%6,%7}, {%8,%9}, {%0,%1,%2,%3};"
        : "+f"(c[0]), "+f"(c[1]), "+f"(c[2]), "+f"(c[3])
        : "r"(a[0]), "r"(a[1]), "r"(a[2]), "r"(a[3]), "r"(b[0]), "r"(b[1]));
}

// ------------------------------ merge+transpose ----------------------------
// Wm^T[n][k] = sum_e wn_e W[e][k][n] -> fp16; bm[n] merged bias (fp32).
__global__ void merge_w(const float* __restrict__ weights,
                        const float* __restrict__ W,
                        const float* __restrict__ b,
                        __half* __restrict__ T,
                        float* __restrict__ bm,
                        int K, int N) {
    __shared__ float tile[32][33];
    float s = 0.f;
#pragma unroll
    for (int e = 0; e < E_EXPERTS; e++) s += weights[e];
    const float inv = 1.f / s;
    float wn[E_EXPERTS];
#pragma unroll
    for (int e = 0; e < E_EXPERTS; e++) wn[e] = weights[e] * inv;

    const int k0 = blockIdx.x * 32, n0 = blockIdx.y * 32;
    for (int ty = threadIdx.y; ty < 32; ty += 8) {
        int k = k0 + ty, n = n0 + threadIdx.x;
        float acc = 0.f;
#pragma unroll
        for (int e = 0; e < E_EXPERTS; e++)
            acc += wn[e] * W[(size_t)e * K * N + (size_t)k * N + n];
        tile[ty][threadIdx.x] = acc;
    }
    if (blockIdx.x == 0 && threadIdx.y == 0) {
        int n = n0 + threadIdx.x;
        float acc = 0.f;
#pragma unroll
        for (int e = 0; e < E_EXPERTS; e++) acc += wn[e] * b[e * N + n];
        bm[n] = acc;
    }
    __syncthreads();
    for (int ty = threadIdx.y; ty < 32; ty += 8) {
        int n = n0 + ty, k = k0 + threadIdx.x;
        T[(size_t)n * K + k] = __float2half_rn(tile[threadIdx.x][ty]);
    }
}

// fp32 -> fp16, vectorized (float4 in, half2x2 out)
__global__ void cast_x(const float4* __restrict__ x, __half2* __restrict__ xh, int n4) {
    int i = blockIdx.x * blockDim.x + threadIdx.x;
    if (i < n4) {
        float4 v = x[i];
        __half2 a, b;
        a.x = __float2half_rn(v.x); a.y = __float2half_rn(v.y);
        b.x = __float2half_rn(v.z); b.y = __float2half_rn(v.w);
        xh[2 * i] = a;
        xh[2 * i + 1] = b;
    }
}

// ------------------------------ HMMA GEMM ----------------------------------
// BM=128, BN=128, BK=32, 256 threads (8 warps: 4 M x 2 N), warp tile 32x64.
// 2-stage cp.async pipeline, one sync per chunk, 2 CTAs per SM.
// smem tiles: A, B; row stride 40 fp16 (80B), conflict-free ldmatrix.
#define BK 32
#define TSTRIDE 40
#define ROWB (TSTRIDE * 2)                  // 80 bytes
#define TILE_B (128 * ROWB)                 // 10240 bytes per tile
#define STAGE_B (2 * TILE_B)                // A, B = 20480 bytes
#define SMEM_DYN (2 * STAGE_B)              // 40960 bytes -> 2 CTAs/SM

template <int OUT_HALF>
__global__ __launch_bounds__(256, 2)
void gemm_hmma(const __half* __restrict__ A, const __half* __restrict__ B,
               const float* __restrict__ bias, const float* __restrict__ alpha,
               float* __restrict__ outF, __half* __restrict__ outH,
               int M, int N, int K) {
    extern __shared__ char smem[];
    const uint32_t sbase = smem_u32(smem);

    const int tid = threadIdx.x;
    const int wid = tid >> 5, lane = tid & 31;
    const int gid = lane >> 2, tg = lane & 3;
    const int warp_m = (wid & 3) * 32;      // 0..96
    const int warp_n = (wid >> 2) * 64;     // 0 or 64
    const int block_m = blockIdx.y * 128;
    const int block_n = blockIdx.x * 128;

    uint32_t a_off[2];
#pragma unroll
    for (int mt = 0; mt < 2; mt++)
        a_off[mt] = ((warp_m + mt * 16 + (lane & 15)) * TSTRIDE + (lane >> 4) * 8) * 2;
    uint32_t b_off[4];
#pragma unroll
    for (int nt2 = 0; nt2 < 4; nt2++)
        b_off[nt2] = ((warp_n + nt2 * 16 + (lane >> 4) * 8 + (lane & 7)) * TSTRIDE +
                      ((lane >> 3) & 1) * 8) * 2;

    float acc[2][8][4];
#pragma unroll
    for (int mt = 0; mt < 2; mt++)
#pragma unroll
        for (int nt = 0; nt < 8; nt++)
#pragma unroll
            for (int j = 0; j < 4; j++) acc[mt][nt][j] = 0.f;

    const int nK = K / BK;
    auto stg = [&](int s) { return sbase + (uint32_t)s * STAGE_B; };

    auto load_stage = [&](int ki, int s) {
        const int k0 = ki * BK;
        const uint32_t base = stg(s);
#pragma unroll
        for (int j = 0; j < 2; j++) {
            int chunk = j * 256 + tid;
            int r = chunk >> 2, c = chunk & 3;
            uint32_t so = (uint32_t)(r * ROWB + c * 16);
            cp16(base + so, A + (size_t)(block_m + r) * K + k0 + c * 8);
            cp16(base + TILE_B + so, B + (size_t)(block_n + r) * K + k0 + c * 8);
        }
    };

    load_stage(0, 0);
    CP_COMMIT();

    for (int i = 0; i < nK; i++) {
        CP_WAIT(0);
        __syncthreads();

        if (i + 1 < nK) load_stage(i + 1, (i + 1) & 1);
        CP_COMMIT();

        const uint32_t tA = stg(i & 1);
        const uint32_t tB = tA + TILE_B;

#pragma unroll
        for (int ks = 0; ks < 2; ks++) {
            const uint32_t kb = ks * 32;
            uint32_t af[2][4];
#pragma unroll
            for (int mt = 0; mt < 2; mt++)
                ldsm4(af[mt][0], af[mt][1], af[mt][2], af[mt][3], tA + a_off[mt] + kb);
#pragma unroll
            for (int nt2 = 0; nt2 < 4; nt2++) {
                uint32_t bf[2][2];
                ldsm4(bf[0][0], bf[0][1], bf[1][0], bf[1][1], tB + b_off[nt2] + kb);
#pragma unroll
                for (int h = 0; h < 2; h++) {
                    const int nt = 2 * nt2 + h;
#pragma unroll
                    for (int mt = 0; mt < 2; mt++)
                        mma_f16(acc[mt][nt], af[mt], bf[h]);
                }
            }
        }
    }

    // ---------------- epilogue: bias + PReLU ------------------------------
#pragma unroll
    for (int mt = 0; mt < 2; mt++) {
        const int r0 = block_m + warp_m + mt * 16 + gid;
#pragma unroll
        for (int nt = 0; nt < 8; nt++) {
            const int n = block_n + warp_n + nt * 8 + tg * 2;
            const float b0 = __ldg(&bias[n]),  b1 = __ldg(&bias[n + 1]);
            const float p0 = __ldg(&alpha[n]), p1 = __ldg(&alpha[n + 1]);
#pragma unroll
            for (int half = 0; half < 2; half++) {
                const int r = r0 + half * 8;
                float v0 = acc[mt][nt][half * 2 + 0] + b0;
                float v1 = acc[mt][nt][half * 2 + 1] + b1;
                v0 = v0 >= 0.f ? v0 : p0 * v0;
                v1 = v1 >= 0.f ? v1 : p1 * v1;
                if (OUT_HALF) {
                    __half2 hh;
                    hh.x = __float2half_rn(v0);
                    hh.y = __float2half_rn(v1);
                    *reinterpret_cast<__half2*>(&outH[(size_t)r * N + n]) = hh;
                } else {
                    float2 o; o.x = v0; o.y = v1;
                    *reinterpret_cast<float2*>(&outF[(size_t)r * N + n]) = o;
                }
            }
        }
    }
}

// ------------------------------ launch -------------------------------------
extern "C" void kernel_launch(void* const* d_in, const int* in_sizes, int n_in,
                              void* d_out, int out_size) {
    const float* x       = (const float*)d_in[0];
    const float* weights = (const float*)d_in[1];
    const float* W0 = (const float*)d_in[2];
    const float* b0 = (const float*)d_in[3];
    const float* a0 = (const float*)d_in[4];
    const float* W1 = (const float*)d_in[5];
    const float* b1 = (const float*)d_in[6];
    const float* a1 = (const float*)d_in[7];
    const float* W2 = (const float*)d_in[8];
    const float* b2 = (const float*)d_in[9];
    const float* a2 = (const float*)d_in[10];
    float* out = (float*)d_out;

    auto sym = [](const void* s) {
        void* p = nullptr;
        cudaGetSymbolAddress(&p, (const void*)s);
        return p;
    };
    __half* xh   = (__half*)sym(g_xh);
    __half* act0 = (__half*)sym(g_a0);
    __half* wt0  = (__half*)sym(g_wt0);
    __half* wt1  = (__half*)sym(g_wt1);
    __half* wt2  = (__half*)sym(g_wt2);
    float* bm0 = (float*)sym(g_bm0);
    float* bm1 = (float*)sym(g_bm1);
    float* bm2 = (float*)sym(g_bm2);

    cudaFuncSetAttribute(gemm_hmma<1>, cudaFuncAttributeMaxDynamicSharedMemorySize, SMEM_DYN);
    cudaFuncSetAttribute(gemm_hmma<0>, cudaFuncAttributeMaxDynamicSharedMemorySize, SMEM_DYN);

    // side stream + events, created once (deterministic work per call)
    static cudaStream_t s1 = nullptr;
    static cudaEvent_t evFork = nullptr, evM1 = nullptr, evM2 = nullptr;
    if (s1 == nullptr) {
        cudaStreamCreateWithFlags(&s1, cudaStreamNonBlocking);
        cudaEventCreateWithFlags(&evFork, cudaEventDisableTiming);
        cudaEventCreateWithFlags(&evM1, cudaEventDisableTiming);
        cudaEventCreateWithFlags(&evM2, cudaEventDisableTiming);
    }

    // main stream (legacy default): merge0 + cast -> gemm0
    merge_w<<<dim3(512 / 32, 1024 / 32), dim3(32, 8)>>>(weights, W0, b0, wt0, bm0, 512, 1024);
    cast_x<<<(8192 * 512 / 4 + 255) / 256, 256>>>(
        (const float4*)x, (__half2*)xh, 8192 * 512 / 4);

    // fork: merges for layers 1,2 overlap gemm0/gemm1
    cudaEventRecord(evFork, 0);
    cudaStreamWaitEvent(s1, evFork, 0);
    merge_w<<<dim3(1024 / 32, 1024 / 32), dim3(32, 8), 0, s1>>>(weights, W1, b1, wt1, bm1, 1024, 1024);
    cudaEventRecord(evM1, s1);
    merge_w<<<dim3(1024 / 32, 512 / 32), dim3(32, 8), 0, s1>>>(weights, W2, b2, wt2, bm2, 1024, 512);
    cudaEventRecord(evM2, s1);

    // layer 0: [8192,512] @ [512,1024] -> fp16 act
    gemm_hmma<1><<<dim3(1024 / 128, M_ROWS / 128), 256, SMEM_DYN>>>(
        xh, wt0, bm0, a0, nullptr, act0, M_ROWS, 1024, 512);

    // layer 1 (needs merge1)
    cudaStreamWaitEvent(0, evM1, 0);
    gemm_hmma<1><<<dim3(1024 / 128, M_ROWS / 128), 256, SMEM_DYN>>>(
        act0, wt1, bm1, a1, nullptr, xh, M_ROWS, 1024, 1024);

    // layer 2 (needs merge2) -> fp32 out; joins side stream back into main
    cudaStreamWaitEvent(0, evM2, 0);
    gemm_hmma<0><<<dim3(512 / 128, M_ROWS / 128), 256, SMEM_DYN>>>(
        xh, wt2, bm2, a2, out, nullptr, M_ROWS, 512, 1024);
}